// round 6
// baseline (speedup 1.0000x reference)
#include <cuda_runtime.h>
#include <cuda_fp16.h>
#include <cstdint>

// ConvNeXt block: dwconv7x7 -> LN -> fused 1x1 MLP (fp16 mma.sync, wt hi/lo) -> residual
#define N_IMG 32
#define C_DIM 128
#define H_DIM 64
#define W_DIM 64
#define D_BOT 512
#define EPS_LN 1e-5f
#define M_TOT (N_IMG * H_DIM * W_DIM)   // 131072

// ---------------- scratch (device globals; no allocs) ----------------------
__device__ __half g_y[(size_t)M_TOT * C_DIM];
__device__ __half g_w1hi[D_BOT * C_DIM];
__device__ __half g_w1lo[D_BOT * C_DIM];
__device__ __half g_w2hi[C_DIM * D_BOT];
__device__ __half g_w2lo[C_DIM * D_BOT];

// ---------------- helpers ---------------------------------------------------
__device__ __forceinline__ uint32_t s2u(const void* p) {
    uint32_t a;
    asm("{ .reg .u64 t; cvta.to.shared.u64 t, %1; cvt.u32.u64 %0, t; }"
        : "=r"(a) : "l"(p));
    return a;
}
__device__ __forceinline__ void cpasync16(uint32_t dst, const void* src) {
    asm volatile("cp.async.cg.shared.global [%0], [%1], 16;" :: "r"(dst), "l"(src));
}
__device__ __forceinline__ void ldsm4(uint32_t* r, uint32_t addr) {
    asm volatile("ldmatrix.sync.aligned.m8n8.x4.shared.b16 {%0,%1,%2,%3}, [%4];"
                 : "=r"(r[0]), "=r"(r[1]), "=r"(r[2]), "=r"(r[3]) : "r"(addr));
}
__device__ __forceinline__ void mma_f16(float* c, uint32_t a0, uint32_t a1,
                                        uint32_t a2, uint32_t a3,
                                        uint32_t b0, uint32_t b1) {
    asm volatile(
        "mma.sync.aligned.m16n8k16.row.col.f32.f16.f16.f32 "
        "{%0,%1,%2,%3}, {%4,%5,%6,%7}, {%8,%9}, {%0,%1,%2,%3};"
        : "+f"(c[0]), "+f"(c[1]), "+f"(c[2]), "+f"(c[3])
        : "r"(a0), "r"(a1), "r"(a2), "r"(a3), "r"(b0), "r"(b1));
}
__device__ __forceinline__ uint32_t packh(__half a, __half b) {
    return (uint32_t)__half_as_ushort(a) | ((uint32_t)__half_as_ushort(b) << 16);
}
__device__ __forceinline__ void split_h(float v, __half& h, __half& l) {
    h = __float2half(v);
    l = __float2half(v - __half2float(h));
}

// ---------------------------------------------------------------------------
// Kernel 0: split weights to fp16 hi/lo
// ---------------------------------------------------------------------------
__global__ __launch_bounds__(256) void wconv_kernel(const float* __restrict__ w1,
                                                    const float* __restrict__ w2) {
    int i = blockIdx.x * 256 + threadIdx.x;
    if (i < D_BOT * C_DIM) {
        __half h, l;
        split_h(w1[i], h, l);
        g_w1hi[i] = h; g_w1lo[i] = l;
        split_h(w2[i], h, l);
        g_w2hi[i] = h; g_w2lo[i] = l;
    }
}

// ---------------------------------------------------------------------------
// Kernel 1: dwconv 7x7 + bias + LN -> fp16 NHWC. Sliding-window registers.
// ---------------------------------------------------------------------------
#define DWLN_SBUF (8 * 2 * 7 * 72)          // floats
#define DWLN_SY   (64 * 129)
#define DWLN_SMEM ((DWLN_SBUF + DWLN_SY) * 4)

__global__ __launch_bounds__(256) void dwln_kernel(
    const float* __restrict__ x, const float* __restrict__ dw_w,
    const float* __restrict__ dw_b, const float* __restrict__ gamma,
    const float* __restrict__ beta)
{
    extern __shared__ float dyn[];
    float* s_buf = dyn;                 // [8 warps][2 ch][7 rows][72]
    float* s_y   = dyn + DWLN_SBUF;     // [64 w][129]

    const int bid = blockIdx.x;
    const int n = bid >> 6;
    const int h = bid & 63;
    const int tid = threadIdx.x;
    const int wg = tid >> 5;
    const int l  = tid & 31;
    const int half = l >> 4;
    const int li = l & 15;

    #pragma unroll 1
    for (int it = 0; it < 8; it++) {
        const int c = wg * 16 + it * 2 + half;
        float* rowbuf = s_buf + (size_t)(wg * 2 + half) * 7 * 72;
        #pragma unroll
        for (int dy = 0; dy < 7; dy++) {
            const int hh = h + dy - 3;
            float4 v = make_float4(0.f, 0.f, 0.f, 0.f);
            if (hh >= 0 && hh < H_DIM)
                v = *reinterpret_cast<const float4*>(
                    x + (((size_t)n * C_DIM + c) * H_DIM + hh) * W_DIM + 4 * li);
            float* rb = rowbuf + dy * 72;
            rb[3 + 4 * li] = v.x;
            rb[4 + 4 * li] = v.y;
            rb[5 + 4 * li] = v.z;
            rb[6 + 4 * li] = v.w;
            if (li == 0)  { rb[0] = 0.f; rb[1] = 0.f; rb[2] = 0.f; }
            if (li == 15) { rb[67] = 0.f; rb[68] = 0.f; rb[69] = 0.f; }
        }
        __syncwarp();

        const float bias = __ldg(&dw_b[c]);
        float acc[4] = {bias, bias, bias, bias};
        const float* wp = dw_w + c * 49;
        #pragma unroll
        for (int dy = 0; dy < 7; dy++) {
            const float* rb = rowbuf + dy * 72 + 4 * li;
            const float4 A = *reinterpret_cast<const float4*>(rb);
            const float4 B = *reinterpret_cast<const float4*>(rb + 4);
            const float2 Cc = *reinterpret_cast<const float2*>(rb + 8);
            const float v[10] = {A.x, A.y, A.z, A.w, B.x, B.y, B.z, B.w, Cc.x, Cc.y};
            #pragma unroll
            for (int dx = 0; dx < 7; dx++) {
                const float wv = __ldg(&wp[dy * 7 + dx]);
                acc[0] += v[dx]     * wv;
                acc[1] += v[dx + 1] * wv;
                acc[2] += v[dx + 2] * wv;
                acc[3] += v[dx + 3] * wv;
            }
        }
        #pragma unroll
        for (int j = 0; j < 4; j++)
            s_y[(4 * li + j) * 129 + c] = acc[j];
        __syncwarp();
    }
    __syncthreads();

    for (int wi = 0; wi < 8; wi++) {
        const int w = wg * 8 + wi;
        float v[4], s = 0.f, sq = 0.f;
        #pragma unroll
        for (int i = 0; i < 4; i++) {
            v[i] = s_y[w * 129 + l + 32 * i];
            s += v[i];
            sq += v[i] * v[i];
        }
        #pragma unroll
        for (int o = 16; o > 0; o >>= 1) {
            s  += __shfl_xor_sync(0xffffffffu, s, o);
            sq += __shfl_xor_sync(0xffffffffu, sq, o);
        }
        const float mu  = s * (1.f / 128.f);
        const float var = sq * (1.f / 128.f) - mu * mu;
        const float rs  = rsqrtf(var + EPS_LN);
        const size_t row = (((size_t)n * H_DIM + h) * W_DIM + w) * C_DIM;
        #pragma unroll
        for (int i = 0; i < 4; i++) {
            const int cix = l + 32 * i;
            const float val = (v[i] - mu) * rs * __ldg(&gamma[cix]) + __ldg(&beta[cix]);
            g_y[row + cix] = __float2half(val);
        }
    }
}

// ---------------------------------------------------------------------------
// Fused MLP megakernel: per 128-row m-tile, loop over 4 hidden chunks:
//   gemm1 partial -> relu/fp16 h panels in smem -> gemm2 partial accumulate.
// smem map: [0, 61440)  staging (2 x {A,Bh,Bl} for gemm1; 2 x {Bh,Bl} for gemm2)
//           [61440, 102400)  h panels (4 x 128 rows x 80B)
// ---------------------------------------------------------------------------
#define ROW2   80
#define MAT2   (128 * ROW2)      // 10240 B
#define ST1    (3 * MAT2)        // 30720 B  (gemm1 stage buffer)
#define HP_OFF (2 * ST1)         // 61440
#define SMEM_F (HP_OFF + 4 * MAT2)   // 102400

__device__ __forceinline__ void stage_mat(const __half* __restrict__ g,
                                          int row0, int ld, int k0, uint32_t dst) {
    const int t = threadIdx.x;
    #pragma unroll
    for (int p = 0; p < 2; p++) {
        const int idx = p * 256 + t;          // 0..511
        const int row = idx >> 2, seg = idx & 3;
        cpasync16(dst + row * ROW2 + seg * 16,
                  g + (size_t)(row0 + row) * ld + k0 + seg * 8);
    }
}

__device__ __forceinline__ void chunk_ab(uint32_t aBase, uint32_t bhBase,
                                         uint32_t blBase, int wm, int wn,
                                         int lane, float c[4][4][4])
{
    #pragma unroll
    for (int ks = 0; ks < 2; ks++) {
        const uint32_t aAddr = aBase + (wm * 64 + (lane & 15)) * ROW2 +
                               ks * 32 + (lane >> 4) * 16;
        const uint32_t bOff = (wn * 32 + (lane & 7) + (lane >> 4) * 8) * ROW2 +
                              ks * 32 + ((lane >> 3) & 1) * 16;
        uint32_t Af[4][4], Bh[2][4], Bl[2][4];
        #pragma unroll
        for (int mf = 0; mf < 4; mf++) ldsm4(Af[mf], aAddr + mf * (16 * ROW2));
        #pragma unroll
        for (int n2 = 0; n2 < 2; n2++) ldsm4(Bh[n2], bhBase + bOff + n2 * (16 * ROW2));
        #pragma unroll
        for (int mf = 0; mf < 4; mf++)
            #pragma unroll
            for (int nf = 0; nf < 4; nf++)
                mma_f16(c[mf][nf], Af[mf][0], Af[mf][1], Af[mf][2], Af[mf][3],
                        Bh[nf >> 1][(nf & 1) * 2], Bh[nf >> 1][(nf & 1) * 2 + 1]);
        #pragma unroll
        for (int n2 = 0; n2 < 2; n2++) ldsm4(Bl[n2], blBase + bOff + n2 * (16 * ROW2));
        #pragma unroll
        for (int mf = 0; mf < 4; mf++)
            #pragma unroll
            for (int nf = 0; nf < 4; nf++)
                mma_f16(c[mf][nf], Af[mf][0], Af[mf][1], Af[mf][2], Af[mf][3],
                        Bl[nf >> 1][(nf & 1) * 2], Bl[nf >> 1][(nf & 1) * 2 + 1]);
    }
}

__global__ __launch_bounds__(256, 1) void fused_mlp(
    const float* __restrict__ x, const float* __restrict__ b1,
    const float* __restrict__ b2, float* __restrict__ out)
{
    extern __shared__ char dsm[];
    const uint32_t sb = s2u(dsm);
    const uint32_t hp = sb + HP_OFF;

    const int tid = threadIdx.x;
    const int wid = tid >> 5, lane = tid & 31;
    const int wm = wid >> 2, wn = wid & 3;
    const int r = lane >> 2, q = lane & 3;
    const int m0 = blockIdx.x << 7;

    float c2[4][4][4];
    #pragma unroll
    for (int a = 0; a < 4; a++)
        #pragma unroll
        for (int b = 0; b < 4; b++)
            #pragma unroll
            for (int d = 0; d < 4; d++) c2[a][b][d] = 0.f;

    #pragma unroll 1
    for (int jc = 0; jc < 4; jc++) {
        const int j0 = jc << 7;
        float c1[4][4][4];
        #pragma unroll
        for (int a = 0; a < 4; a++)
            #pragma unroll
            for (int b = 0; b < 4; b++)
                #pragma unroll
                for (int d = 0; d < 4; d++) c1[a][b][d] = 0.f;

        // ---- gemm1: y(m-tile) x W1[j0..j0+128)^T, K = 128 (4 chunks) ----
        stage_mat(g_y,    m0, C_DIM, 0, sb);
        stage_mat(g_w1hi, j0, C_DIM, 0, sb + MAT2);
        stage_mat(g_w1lo, j0, C_DIM, 0, sb + 2 * MAT2);
        asm volatile("cp.async.commit_group;");
        #pragma unroll 1
        for (int i = 0; i < 4; i++) {
            if (i + 1 < 4) {
                const uint32_t nb = sb + ((i + 1) & 1) * ST1;
                stage_mat(g_y,    m0, C_DIM, (i + 1) * 32, nb);
                stage_mat(g_w1hi, j0, C_DIM, (i + 1) * 32, nb + MAT2);
                stage_mat(g_w1lo, j0, C_DIM, (i + 1) * 32, nb + 2 * MAT2);
                asm volatile("cp.async.commit_group;");
                asm volatile("cp.async.wait_group 1;");
            } else {
                asm volatile("cp.async.wait_group 0;");
            }
            __syncthreads();
            const uint32_t b = sb + (i & 1) * ST1;
            chunk_ab(b, b + MAT2, b + 2 * MAT2, wm, wn, lane, c1);
            __syncthreads();
        }

        // ---- h epilogue: bias + relu -> fp16 into smem panel wn ----
        #pragma unroll
        for (int nf = 0; nf < 4; nf++) {
            const int cp = nf * 8 + 2 * q;              // col within panel
            const float2 bb = *reinterpret_cast<const float2*>(b1 + j0 + wn * 32 + cp);
            #pragma unroll
            for (int mf = 0; mf < 4; mf++)
                #pragma unroll
                for (int hf = 0; hf < 2; hf++) {
                    const int row = wm * 64 + mf * 16 + r + 8 * hf;
                    const float v0 = fmaxf(c1[mf][nf][2 * hf]     + bb.x, 0.f);
                    const float v1 = fmaxf(c1[mf][nf][2 * hf + 1] + bb.y, 0.f);
                    asm volatile("st.shared.b32 [%0], %1;" ::
                        "r"(hp + wn * MAT2 + row * ROW2 + cp * 2),
                        "r"(packh(__float2half(v0), __float2half(v1))) : "memory");
                }
        }
        __syncthreads();

        // ---- gemm2 partial: h panels x W2[:, j0..j0+128)^T (4 chunks) ----
        stage_mat(g_w2hi, 0, D_BOT, j0, sb);
        stage_mat(g_w2lo, 0, D_BOT, j0, sb + MAT2);
        asm volatile("cp.async.commit_group;");
        #pragma unroll 1
        for (int p = 0; p < 4; p++) {
            if (p + 1 < 4) {
                const uint32_t nb = sb + ((p + 1) & 1) * (2 * MAT2);
                stage_mat(g_w2hi, 0, D_BOT, j0 + (p + 1) * 32, nb);
                stage_mat(g_w2lo, 0, D_BOT, j0 + (p + 1) * 32, nb + MAT2);
                asm volatile("cp.async.commit_group;");
                asm volatile("cp.async.wait_group 1;");
            } else {
                asm volatile("cp.async.wait_group 0;");
            }
            __syncthreads();
            const uint32_t b = sb + (p & 1) * (2 * MAT2);
            chunk_ab(hp + p * MAT2, b, b + MAT2, wm, wn, lane, c2);
            __syncthreads();
        }
    }

    // ---- final epilogue: transpose via smem, NCHW store + bias + residual ----
    float* sC = (float*)dsm;                  // 64 x 132 floats per half
    const int n  = m0 >> 12;
    const int sp0 = m0 & 4095;

    #pragma unroll 1
    for (int hh = 0; hh < 2; hh++) {
        if ((wn >> 1) == hh) {
            #pragma unroll
            for (int nf = 0; nf < 4; nf++) {
                const int cl = (wn & 1) * 32 + nf * 8 + 2 * q;
                #pragma unroll
                for (int mf = 0; mf < 4; mf++)
                    #pragma unroll
                    for (int hf = 0; hf < 2; hf++) {
                        const int ml = wm * 64 + mf * 16 + r + 8 * hf;
                        sC[cl * 132 + ml]       = c2[mf][nf][2 * hf];
                        sC[(cl + 1) * 132 + ml] = c2[mf][nf][2 * hf + 1];
                    }
            }
        }
        __syncthreads();
        #pragma unroll
        for (int qi = 0; qi < 8; qi++) {
            const int idx = qi * 256 + tid;
            const int j   = idx >> 5;
            const int m4  = (idx & 31) << 2;
            const int ch  = hh * 64 + j;
            const float bc = __ldg(&b2[ch]);
            const size_t g = ((size_t)(n * C_DIM + ch) << 12) + sp0 + m4;
            float4 v  = *reinterpret_cast<const float4*>(&sC[j * 132 + m4]);
            float4 xv = *reinterpret_cast<const float4*>(x + g);
            float4 o;
            o.x = v.x + xv.x + bc;
            o.y = v.y + xv.y + bc;
            o.z = v.z + xv.z + bc;
            o.w = v.w + xv.w + bc;
            *reinterpret_cast<float4*>(out + g) = o;
        }
        __syncthreads();
    }
}

// ---------------------------------------------------------------------------
extern "C" void kernel_launch(void* const* d_in, const int* in_sizes, int n_in,
                              void* d_out, int out_size)
{
    const float* x     = (const float*)d_in[0];
    const float* dw_w  = (const float*)d_in[1];
    const float* dw_b  = (const float*)d_in[2];
    const float* gamma = (const float*)d_in[3];
    const float* beta  = (const float*)d_in[4];
    const float* pw1_w = (const float*)d_in[5];
    const float* pw1_b = (const float*)d_in[6];
    const float* pw2_w = (const float*)d_in[7];
    const float* pw2_b = (const float*)d_in[8];
    float* out = (float*)d_out;

    static bool attr_done = false;
    if (!attr_done) {
        cudaFuncSetAttribute(dwln_kernel, cudaFuncAttributeMaxDynamicSharedMemorySize, DWLN_SMEM);
        cudaFuncSetAttribute(fused_mlp, cudaFuncAttributeMaxDynamicSharedMemorySize, SMEM_F);
        attr_done = true;
    }

    wconv_kernel<<<(D_BOT * C_DIM + 255) / 256, 256>>>(pw1_w, pw2_w);
    dwln_kernel<<<N_IMG * H_DIM, 256, DWLN_SMEM>>>(x, dw_w, dw_b, gamma, beta);
    fused_mlp<<<M_TOT / 128, 256, SMEM_F>>>(x, pw1_b, pw2_b, out);
}

// round 7
// speedup vs baseline: 1.2140x; 1.2140x over previous
#include <cuda_runtime.h>
#include <cuda_fp16.h>
#include <cstdint>

// ConvNeXt block: dwconv7x7 -> LN -> 1x1 MLP (fp16 mma.sync, 1-term) -> residual
#define N_IMG 32
#define C_DIM 128
#define H_DIM 64
#define W_DIM 64
#define D_BOT 512
#define EPS_LN 1e-5f
#define M_TOT (N_IMG * H_DIM * W_DIM)   // 131072

// ---------------- scratch (device globals; no allocs) ----------------------
__device__ __half g_y[(size_t)M_TOT * C_DIM];
__device__ __half g_h[(size_t)M_TOT * D_BOT];
__device__ __half g_w1h[D_BOT * C_DIM];
__device__ __half g_w2h[C_DIM * D_BOT];

// ---------------- helpers ---------------------------------------------------
__device__ __forceinline__ uint32_t s2u(const void* p) {
    uint32_t a;
    asm("{ .reg .u64 t; cvta.to.shared.u64 t, %1; cvt.u32.u64 %0, t; }"
        : "=r"(a) : "l"(p));
    return a;
}
__device__ __forceinline__ void cpasync16(uint32_t dst, const void* src) {
    asm volatile("cp.async.cg.shared.global [%0], [%1], 16;" :: "r"(dst), "l"(src));
}
__device__ __forceinline__ void ldsm4(uint32_t* r, uint32_t addr) {
    asm volatile("ldmatrix.sync.aligned.m8n8.x4.shared.b16 {%0,%1,%2,%3}, [%4];"
                 : "=r"(r[0]), "=r"(r[1]), "=r"(r[2]), "=r"(r[3]) : "r"(addr));
}
__device__ __forceinline__ void mma_f16(float* c, uint32_t a0, uint32_t a1,
                                        uint32_t a2, uint32_t a3,
                                        uint32_t b0, uint32_t b1) {
    asm volatile(
        "mma.sync.aligned.m16n8k16.row.col.f32.f16.f16.f32 "
        "{%0,%1,%2,%3}, {%4,%5,%6,%7}, {%8,%9}, {%0,%1,%2,%3};"
        : "+f"(c[0]), "+f"(c[1]), "+f"(c[2]), "+f"(c[3])
        : "r"(a0), "r"(a1), "r"(a2), "r"(a3), "r"(b0), "r"(b1));
}
__device__ __forceinline__ uint32_t packh(__half a, __half b) {
    return (uint32_t)__half_as_ushort(a) | ((uint32_t)__half_as_ushort(b) << 16);
}

// ---------------------------------------------------------------------------
// Kernel 0: weights -> fp16
// ---------------------------------------------------------------------------
__global__ __launch_bounds__(256) void wconv_kernel(const float* __restrict__ w1,
                                                    const float* __restrict__ w2) {
    int i = blockIdx.x * 256 + threadIdx.x;
    if (i < D_BOT * C_DIM) {
        g_w1h[i] = __float2half(w1[i]);
        g_w2h[i] = __float2half(w2[i]);
    }
}

// ---------------------------------------------------------------------------
// Kernel 1: dwconv 7x7 + bias + LN -> fp16 NHWC. (unchanged from R5)
// ---------------------------------------------------------------------------
#define DWLN_SBUF (8 * 2 * 7 * 72)          // floats
#define DWLN_SY   (64 * 129)
#define DWLN_SMEM ((DWLN_SBUF + DWLN_SY) * 4)

__global__ __launch_bounds__(256) void dwln_kernel(
    const float* __restrict__ x, const float* __restrict__ dw_w,
    const float* __restrict__ dw_b, const float* __restrict__ gamma,
    const float* __restrict__ beta)
{
    extern __shared__ float dyn[];
    float* s_buf = dyn;                 // [8 warps][2 ch][7 rows][72]
    float* s_y   = dyn + DWLN_SBUF;     // [64 w][129]

    const int bid = blockIdx.x;
    const int n = bid >> 6;
    const int h = bid & 63;
    const int tid = threadIdx.x;
    const int wg = tid >> 5;
    const int l  = tid & 31;
    const int half = l >> 4;
    const int li = l & 15;

    #pragma unroll 1
    for (int it = 0; it < 8; it++) {
        const int c = wg * 16 + it * 2 + half;
        float* rowbuf = s_buf + (size_t)(wg * 2 + half) * 7 * 72;
        #pragma unroll
        for (int dy = 0; dy < 7; dy++) {
            const int hh = h + dy - 3;
            float4 v = make_float4(0.f, 0.f, 0.f, 0.f);
            if (hh >= 0 && hh < H_DIM)
                v = *reinterpret_cast<const float4*>(
                    x + (((size_t)n * C_DIM + c) * H_DIM + hh) * W_DIM + 4 * li);
            float* rb = rowbuf + dy * 72;
            rb[3 + 4 * li] = v.x;
            rb[4 + 4 * li] = v.y;
            rb[5 + 4 * li] = v.z;
            rb[6 + 4 * li] = v.w;
            if (li == 0)  { rb[0] = 0.f; rb[1] = 0.f; rb[2] = 0.f; }
            if (li == 15) { rb[67] = 0.f; rb[68] = 0.f; rb[69] = 0.f; }
        }
        __syncwarp();

        const float bias = __ldg(&dw_b[c]);
        float acc[4] = {bias, bias, bias, bias};
        const float* wp = dw_w + c * 49;
        #pragma unroll
        for (int dy = 0; dy < 7; dy++) {
            const float* rb = rowbuf + dy * 72 + 4 * li;
            const float4 A = *reinterpret_cast<const float4*>(rb);
            const float4 B = *reinterpret_cast<const float4*>(rb + 4);
            const float2 Cc = *reinterpret_cast<const float2*>(rb + 8);
            const float v[10] = {A.x, A.y, A.z, A.w, B.x, B.y, B.z, B.w, Cc.x, Cc.y};
            #pragma unroll
            for (int dx = 0; dx < 7; dx++) {
                const float wv = __ldg(&wp[dy * 7 + dx]);
                acc[0] += v[dx]     * wv;
                acc[1] += v[dx + 1] * wv;
                acc[2] += v[dx + 2] * wv;
                acc[3] += v[dx + 3] * wv;
            }
        }
        #pragma unroll
        for (int j = 0; j < 4; j++)
            s_y[(4 * li + j) * 129 + c] = acc[j];
        __syncwarp();
    }
    __syncthreads();

    for (int wi = 0; wi < 8; wi++) {
        const int w = wg * 8 + wi;
        float v[4], s = 0.f, sq = 0.f;
        #pragma unroll
        for (int i = 0; i < 4; i++) {
            v[i] = s_y[w * 129 + l + 32 * i];
            s += v[i];
            sq += v[i] * v[i];
        }
        #pragma unroll
        for (int o = 16; o > 0; o >>= 1) {
            s  += __shfl_xor_sync(0xffffffffu, s, o);
            sq += __shfl_xor_sync(0xffffffffu, sq, o);
        }
        const float mu  = s * (1.f / 128.f);
        const float var = sq * (1.f / 128.f) - mu * mu;
        const float rs  = rsqrtf(var + EPS_LN);
        const size_t row = (((size_t)n * H_DIM + h) * W_DIM + w) * C_DIM;
        #pragma unroll
        for (int i = 0; i < 4; i++) {
            const int cix = l + 32 * i;
            const float val = (v[i] - mu) * rs * __ldg(&gamma[cix]) + __ldg(&beta[cix]);
            g_y[row + cix] = __float2half(val);
        }
    }
}

// ---------------------------------------------------------------------------
// mma.sync GEMM: CTA 64x128, 8 warps (2x4), warp tile 32x32, K-chunk 32.
// smem per buffer: A 64 rows x 80B + B 128 rows x 80B. Double-buffered.
// ---------------------------------------------------------------------------
#define ROWB 80
#define AMAT (64 * ROWB)         // 5120 B
#define BMAT (128 * ROWB)        // 10240 B
#define BUFB (AMAT + BMAT)       // 15360 B
#define SMEM_G (2 * BUFB)        // 30720 B

__device__ __forceinline__ void stage_ab(const __half* __restrict__ A,
                                         const __half* __restrict__ B,
                                         int lda, int ldb, int arow0, int brow0,
                                         int k0, uint32_t buf)
{
    const int t = threadIdx.x;
    {
        const int row = t >> 2, seg = t & 3;
        cpasync16(buf + row * ROWB + seg * 16,
                  A + (size_t)(arow0 + row) * lda + k0 + seg * 8);
    }
    #pragma unroll
    for (int p = 0; p < 2; p++) {
        const int idx = p * 256 + t;
        const int row = idx >> 2, seg = idx & 3;
        cpasync16(buf + AMAT + row * ROWB + seg * 16,
                  B + (size_t)(brow0 + row) * ldb + k0 + seg * 8);
    }
}

__device__ __forceinline__ void chunk1(uint32_t buf, int wm, int wn, int lane,
                                       float c[2][4][4])
{
    #pragma unroll
    for (int ks = 0; ks < 2; ks++) {
        const uint32_t aAddr = buf + (wm * 32 + (lane & 15)) * ROWB +
                               ks * 32 + (lane >> 4) * 16;
        const uint32_t bAddr = buf + AMAT +
                               (wn * 32 + (lane & 7) + (lane >> 4) * 8) * ROWB +
                               ks * 32 + ((lane >> 3) & 1) * 16;
        uint32_t Af[2][4], Bf[2][4];
        #pragma unroll
        for (int mf = 0; mf < 2; mf++) ldsm4(Af[mf], aAddr + mf * (16 * ROWB));
        #pragma unroll
        for (int n2 = 0; n2 < 2; n2++) ldsm4(Bf[n2], bAddr + n2 * (16 * ROWB));
        #pragma unroll
        for (int mf = 0; mf < 2; mf++)
            #pragma unroll
            for (int nf = 0; nf < 4; nf++)
                mma_f16(c[mf][nf], Af[mf][0], Af[mf][1], Af[mf][2], Af[mf][3],
                        Bf[nf >> 1][(nf & 1) * 2], Bf[nf >> 1][(nf & 1) * 2 + 1]);
    }
}

template <int NC>
__device__ __forceinline__ void run_gemm64(
    const __half* A, const __half* B, int lda, int ldb, int arow0, int brow0,
    uint32_t sbase, float c[2][4][4])
{
    const int tid = threadIdx.x;
    const int wid = tid >> 5, lane = tid & 31;
    const int wm = wid >> 2, wn = wid & 3;

    stage_ab(A, B, lda, ldb, arow0, brow0, 0, sbase);
    asm volatile("cp.async.commit_group;");

    #pragma unroll 1
    for (int i = 0; i < NC; i++) {
        if (i + 1 < NC) {
            stage_ab(A, B, lda, ldb, arow0, brow0, (i + 1) * 32,
                     sbase + ((i + 1) & 1) * BUFB);
            asm volatile("cp.async.commit_group;");
            asm volatile("cp.async.wait_group 1;");
        } else {
            asm volatile("cp.async.wait_group 0;");
        }
        __syncthreads();
        chunk1(sbase + (i & 1) * BUFB, wm, wn, lane, c);
        __syncthreads();
    }
}

// ---------------------------------------------------------------------------
// Kernel 2: h = relu(y @ W1^T + b1) -> fp16
// ---------------------------------------------------------------------------
__global__ __launch_bounds__(256, 3) void gemm1_mma(const float* __restrict__ bias1)
{
    extern __shared__ char dsm[];
    float c[2][4][4];
    #pragma unroll
    for (int a = 0; a < 2; a++)
        #pragma unroll
        for (int b = 0; b < 4; b++)
            #pragma unroll
            for (int d = 0; d < 4; d++) c[a][b][d] = 0.f;

    const int j0 = blockIdx.x << 7;
    const int m0 = blockIdx.y << 6;

    run_gemm64<4>(g_y, g_w1h, C_DIM, C_DIM, m0, j0, s2u(dsm), c);

    const int tid = threadIdx.x;
    const int wid = tid >> 5, lane = tid & 31;
    const int wm = wid >> 2, wn = wid & 3;
    const int r = lane >> 2, q = lane & 3;

    uint32_t* dh = (uint32_t*)g_h;
    #pragma unroll
    for (int nf = 0; nf < 4; nf++) {
        const int jc = j0 + wn * 32 + nf * 8 + 2 * q;
        const float2 bb = *reinterpret_cast<const float2*>(bias1 + jc);
        #pragma unroll
        for (int mf = 0; mf < 2; mf++)
            #pragma unroll
            for (int hf = 0; hf < 2; hf++) {
                const int row = m0 + wm * 32 + mf * 16 + r + 8 * hf;
                const float v0 = fmaxf(c[mf][nf][2 * hf]     + bb.x, 0.f);
                const float v1 = fmaxf(c[mf][nf][2 * hf + 1] + bb.y, 0.f);
                dh[(size_t)row * (D_BOT / 2) + (jc >> 1)] =
                    packh(__float2half(v0), __float2half(v1));
            }
    }
}

// ---------------------------------------------------------------------------
// Kernel 3: out = x + (h @ W2^T + b2), NCHW + residual
// ---------------------------------------------------------------------------
__global__ __launch_bounds__(256, 3) void gemm2_mma(const float* __restrict__ x,
                                                    const float* __restrict__ b2,
                                                    float* __restrict__ out)
{
    extern __shared__ char dsm[];
    float c[2][4][4];
    #pragma unroll
    for (int a = 0; a < 2; a++)
        #pragma unroll
        for (int b = 0; b < 4; b++)
            #pragma unroll
            for (int d = 0; d < 4; d++) c[a][b][d] = 0.f;

    const int m0 = blockIdx.x << 6;

    run_gemm64<16>(g_h, g_w2h, D_BOT, D_BOT, m0, 0, s2u(dsm), c);

    const int tid = threadIdx.x;
    const int wid = tid >> 5, lane = tid & 31;
    const int wm = wid >> 2, wn = wid & 3;
    const int r = lane >> 2, q = lane & 3;

    float* sC = (float*)dsm;                  // 64 ch x 68 floats per half
    const int n  = m0 >> 12;
    const int sp0 = m0 & 4095;

    #pragma unroll 1
    for (int hh = 0; hh < 2; hh++) {
        if ((wn >> 1) == hh) {
            #pragma unroll
            for (int nf = 0; nf < 4; nf++) {
                const int cl = (wn & 1) * 32 + nf * 8 + 2 * q;
                #pragma unroll
                for (int mf = 0; mf < 2; mf++)
                    #pragma unroll
                    for (int hf = 0; hf < 2; hf++) {
                        const int ml = wm * 32 + mf * 16 + r + 8 * hf;
                        sC[cl * 68 + ml]       = c[mf][nf][2 * hf];
                        sC[(cl + 1) * 68 + ml] = c[mf][nf][2 * hf + 1];
                    }
            }
        }
        __syncthreads();
        #pragma unroll
        for (int qi = 0; qi < 4; qi++) {
            const int idx = qi * 256 + tid;
            const int j   = idx >> 4;          // 0..63
            const int m4  = (idx & 15) << 2;   // 0..60
            const int ch  = hh * 64 + j;
            const float bc = __ldg(&b2[ch]);
            const size_t g = ((size_t)(n * C_DIM + ch) << 12) + sp0 + m4;
            float4 v  = *reinterpret_cast<const float4*>(&sC[j * 68 + m4]);
            float4 xv = *reinterpret_cast<const float4*>(x + g);
            float4 o;
            o.x = v.x + xv.x + bc;
            o.y = v.y + xv.y + bc;
            o.z = v.z + xv.z + bc;
            o.w = v.w + xv.w + bc;
            *reinterpret_cast<float4*>(out + g) = o;
        }
        __syncthreads();
    }
}

// ---------------------------------------------------------------------------
extern "C" void kernel_launch(void* const* d_in, const int* in_sizes, int n_in,
                              void* d_out, int out_size)
{
    const float* x     = (const float*)d_in[0];
    const float* dw_w  = (const float*)d_in[1];
    const float* dw_b  = (const float*)d_in[2];
    const float* gamma = (const float*)d_in[3];
    const float* beta  = (const float*)d_in[4];
    const float* pw1_w = (const float*)d_in[5];
    const float* pw1_b = (const float*)d_in[6];
    const float* pw2_w = (const float*)d_in[7];
    const float* pw2_b = (const float*)d_in[8];
    float* out = (float*)d_out;

    static bool attr_done = false;
    if (!attr_done) {
        cudaFuncSetAttribute(dwln_kernel, cudaFuncAttributeMaxDynamicSharedMemorySize, DWLN_SMEM);
        cudaFuncSetAttribute(gemm1_mma, cudaFuncAttributeMaxDynamicSharedMemorySize, SMEM_G);
        cudaFuncSetAttribute(gemm2_mma, cudaFuncAttributeMaxDynamicSharedMemorySize, SMEM_G);
        attr_done = true;
    }

    wconv_kernel<<<(D_BOT * C_DIM + 255) / 256, 256>>>(pw1_w, pw2_w);
    dwln_kernel<<<N_IMG * H_DIM, 256, DWLN_SMEM>>>(x, dw_w, dw_b, gamma, beta);
    gemm1_mma<<<dim3(D_BOT / 128, M_TOT / 64), 256, SMEM_G>>>(pw1_b);
    gemm2_mma<<<M_TOT / 64, 256, SMEM_G>>>(x, pw2_b, out);
}

// round 8
// speedup vs baseline: 1.2929x; 1.0650x over previous
#include <cuda_runtime.h>
#include <cuda_fp16.h>
#include <cstdint>

// ConvNeXt block: dwconv7x7 -> LN -> 1x1 MLP (fp16 mma.sync, 1-term) -> residual
#define N_IMG 32
#define C_DIM 128
#define H_DIM 64
#define W_DIM 64
#define D_BOT 512
#define EPS_LN 1e-5f
#define M_TOT (N_IMG * H_DIM * W_DIM)   // 131072

// ---------------- scratch (device globals; no allocs) ----------------------
__device__ __half g_y[(size_t)M_TOT * C_DIM];
__device__ __half g_h[(size_t)M_TOT * D_BOT];
__device__ __half g_w1h[D_BOT * C_DIM];
__device__ __half g_w2h[C_DIM * D_BOT];

// ---------------- helpers ---------------------------------------------------
__device__ __forceinline__ uint32_t s2u(const void* p) {
    uint32_t a;
    asm("{ .reg .u64 t; cvta.to.shared.u64 t, %1; cvt.u32.u64 %0, t; }"
        : "=r"(a) : "l"(p));
    return a;
}
__device__ __forceinline__ void cpasync16(uint32_t dst, const void* src) {
    asm volatile("cp.async.cg.shared.global [%0], [%1], 16;" :: "r"(dst), "l"(src));
}
__device__ __forceinline__ void ldsm4(uint32_t* r, uint32_t addr) {
    asm volatile("ldmatrix.sync.aligned.m8n8.x4.shared.b16 {%0,%1,%2,%3}, [%4];"
                 : "=r"(r[0]), "=r"(r[1]), "=r"(r[2]), "=r"(r[3]) : "r"(addr));
}
__device__ __forceinline__ void mma_f16(float* c, uint32_t a0, uint32_t a1,
                                        uint32_t a2, uint32_t a3,
                                        uint32_t b0, uint32_t b1) {
    asm volatile(
        "mma.sync.aligned.m16n8k16.row.col.f32.f16.f16.f32 "
        "{%0,%1,%2,%3}, {%4,%5,%6,%7}, {%8,%9}, {%0,%1,%2,%3};"
        : "+f"(c[0]), "+f"(c[1]), "+f"(c[2]), "+f"(c[3])
        : "r"(a0), "r"(a1), "r"(a2), "r"(a3), "r"(b0), "r"(b1));
}
__device__ __forceinline__ uint32_t packh(__half a, __half b) {
    return (uint32_t)__half_as_ushort(a) | ((uint32_t)__half_as_ushort(b) << 16);
}

// ---------------------------------------------------------------------------
// Kernel 0: weights -> fp16
// ---------------------------------------------------------------------------
__global__ __launch_bounds__(256) void wconv_kernel(const float* __restrict__ w1,
                                                    const float* __restrict__ w2) {
    int i = blockIdx.x * 256 + threadIdx.x;
    if (i < D_BOT * C_DIM) {
        g_w1h[i] = __float2half(w1[i]);
        g_w2h[i] = __float2half(w2[i]);
    }
}

// ---------------------------------------------------------------------------
// Kernel 1: dwconv 7x7 + bias + LN -> fp16 NHWC.
// CTA = (n, 2 output rows). Stage 8 input rows once; dy-outer accumulation
// feeds both output rows from each staged row window.
// ---------------------------------------------------------------------------
#define DW_SLOT  (8 * 72)                    // floats per half-warp slot
#define DW_SBUF  (16 * DW_SLOT)              // 9216 floats
#define DW_SY    (128 * 129)                 // 16512 floats
#define DWLN_SMEM ((DW_SBUF + DW_SY) * 4)    // 102912 B

__global__ __launch_bounds__(256) void dwln_kernel(
    const float* __restrict__ x, const float* __restrict__ dw_w,
    const float* __restrict__ dw_b, const float* __restrict__ gamma,
    const float* __restrict__ beta)
{
    extern __shared__ float dyn[];
    float* s_buf = dyn;                 // [16 slots][8 rows][72]
    float* s_y   = dyn + DW_SBUF;       // [128 pos][129]

    const int b = blockIdx.x;
    const int n  = b >> 5;
    const int h0 = (b & 31) << 1;
    const int tid = threadIdx.x;
    const int wg = tid >> 5;
    const int l  = tid & 31;
    const int half = l >> 4;
    const int li = l & 15;
    float* rowbuf = s_buf + (size_t)(wg * 2 + half) * DW_SLOT;

    #pragma unroll 1
    for (int it = 0; it < 8; it++) {
        const int c = wg * 16 + it * 2 + half;
        // stage 8 rows: hh = h0-3 .. h0+4 (zero outside image)
        #pragma unroll
        for (int dy = 0; dy < 8; dy++) {
            const int hh = h0 - 3 + dy;
            float4 v = make_float4(0.f, 0.f, 0.f, 0.f);
            if (hh >= 0 && hh < H_DIM)
                v = *reinterpret_cast<const float4*>(
                    x + (((size_t)n * C_DIM + c) * H_DIM + hh) * W_DIM + 4 * li);
            float* rb = rowbuf + dy * 72;
            rb[3 + 4 * li] = v.x;
            rb[4 + 4 * li] = v.y;
            rb[5 + 4 * li] = v.z;
            rb[6 + 4 * li] = v.w;
            if (li == 0)  { rb[0] = 0.f; rb[1] = 0.f; rb[2] = 0.f; }
            if (li == 15) { rb[67] = 0.f; rb[68] = 0.f; rb[69] = 0.f; }
        }
        __syncwarp();

        const float bias = __ldg(&dw_b[c]);
        float a0[4] = {bias, bias, bias, bias};     // output row h0
        float a1[4] = {bias, bias, bias, bias};     // output row h0+1
        const float* wp = dw_w + c * 49;
        #pragma unroll
        for (int dy = 0; dy < 8; dy++) {
            const float* rb = rowbuf + dy * 72 + 4 * li;
            const float4 A = *reinterpret_cast<const float4*>(rb);
            const float4 B = *reinterpret_cast<const float4*>(rb + 4);
            const float2 Cc = *reinterpret_cast<const float2*>(rb + 8);
            const float v[10] = {A.x, A.y, A.z, A.w, B.x, B.y, B.z, B.w, Cc.x, Cc.y};
            if (dy < 7) {
                const float* w0 = wp + dy * 7;
                #pragma unroll
                for (int dx = 0; dx < 7; dx++) {
                    const float wv = __ldg(&w0[dx]);
                    a0[0] += v[dx]     * wv;
                    a0[1] += v[dx + 1] * wv;
                    a0[2] += v[dx + 2] * wv;
                    a0[3] += v[dx + 3] * wv;
                }
            }
            if (dy >= 1) {
                const float* w1 = wp + (dy - 1) * 7;
                #pragma unroll
                for (int dx = 0; dx < 7; dx++) {
                    const float wv = __ldg(&w1[dx]);
                    a1[0] += v[dx]     * wv;
                    a1[1] += v[dx + 1] * wv;
                    a1[2] += v[dx + 2] * wv;
                    a1[3] += v[dx + 3] * wv;
                }
            }
        }
        #pragma unroll
        for (int j = 0; j < 4; j++) {
            s_y[(4 * li + j) * 129 + c]        = a0[j];
            s_y[(64 + 4 * li + j) * 129 + c]   = a1[j];
        }
        __syncwarp();
    }
    __syncthreads();

    // LayerNorm over 128 channels; warp wg handles positions wg*16..wg*16+15
    for (int wi = 0; wi < 16; wi++) {
        const int p = wg * 16 + wi;             // 0..127 (row = p>>6, w = p&63)
        float v[4], s = 0.f, sq = 0.f;
        #pragma unroll
        for (int i = 0; i < 4; i++) {
            v[i] = s_y[p * 129 + l + 32 * i];
            s += v[i];
            sq += v[i] * v[i];
        }
        #pragma unroll
        for (int o = 16; o > 0; o >>= 1) {
            s  += __shfl_xor_sync(0xffffffffu, s, o);
            sq += __shfl_xor_sync(0xffffffffu, sq, o);
        }
        const float mu  = s * (1.f / 128.f);
        const float var = sq * (1.f / 128.f) - mu * mu;
        const float rs  = rsqrtf(var + EPS_LN);
        const size_t row =
            (((size_t)n * H_DIM + h0 + (p >> 6)) * W_DIM + (p & 63)) * C_DIM;
        #pragma unroll
        for (int i = 0; i < 4; i++) {
            const int cix = l + 32 * i;
            const float val = (v[i] - mu) * rs * __ldg(&gamma[cix]) + __ldg(&beta[cix]);
            g_y[row + cix] = __float2half(val);
        }
    }
}

// ---------------------------------------------------------------------------
// mma.sync GEMM: CTA 64x128, 8 warps (2x4), warp tile 32x32, K-chunk 32.
// ---------------------------------------------------------------------------
#define ROWB 80
#define AMAT (64 * ROWB)         // 5120 B
#define BMAT (128 * ROWB)        // 10240 B
#define BUFB (AMAT + BMAT)       // 15360 B
#define SMEM_G (2 * BUFB)        // 30720 B

__device__ __forceinline__ void stage_ab(const __half* __restrict__ A,
                                         const __half* __restrict__ B,
                                         int lda, int ldb, int arow0, int brow0,
                                         int k0, uint32_t buf)
{
    const int t = threadIdx.x;
    {
        const int row = t >> 2, seg = t & 3;
        cpasync16(buf + row * ROWB + seg * 16,
                  A + (size_t)(arow0 + row) * lda + k0 + seg * 8);
    }
    #pragma unroll
    for (int p = 0; p < 2; p++) {
        const int idx = p * 256 + t;
        const int row = idx >> 2, seg = idx & 3;
        cpasync16(buf + AMAT + row * ROWB + seg * 16,
                  B + (size_t)(brow0 + row) * ldb + k0 + seg * 8);
    }
}

__device__ __forceinline__ void chunk1(uint32_t buf, int wm, int wn, int lane,
                                       float c[2][4][4])
{
    #pragma unroll
    for (int ks = 0; ks < 2; ks++) {
        const uint32_t aAddr = buf + (wm * 32 + (lane & 15)) * ROWB +
                               ks * 32 + (lane >> 4) * 16;
        const uint32_t bAddr = buf + AMAT +
                               (wn * 32 + (lane & 7) + (lane >> 4) * 8) * ROWB +
                               ks * 32 + ((lane >> 3) & 1) * 16;
        uint32_t Af[2][4], Bf[2][4];
        #pragma unroll
        for (int mf = 0; mf < 2; mf++) ldsm4(Af[mf], aAddr + mf * (16 * ROWB));
        #pragma unroll
        for (int n2 = 0; n2 < 2; n2++) ldsm4(Bf[n2], bAddr + n2 * (16 * ROWB));
        #pragma unroll
        for (int mf = 0; mf < 2; mf++)
            #pragma unroll
            for (int nf = 0; nf < 4; nf++)
                mma_f16(c[mf][nf], Af[mf][0], Af[mf][1], Af[mf][2], Af[mf][3],
                        Bf[nf >> 1][(nf & 1) * 2], Bf[nf >> 1][(nf & 1) * 2 + 1]);
    }
}

template <int NC>
__device__ __forceinline__ void run_gemm64(
    const __half* A, const __half* B, int lda, int ldb, int arow0, int brow0,
    uint32_t sbase, float c[2][4][4])
{
    const int tid = threadIdx.x;
    const int wid = tid >> 5, lane = tid & 31;
    const int wm = wid >> 2, wn = wid & 3;

    stage_ab(A, B, lda, ldb, arow0, brow0, 0, sbase);
    asm volatile("cp.async.commit_group;");

    #pragma unroll 1
    for (int i = 0; i < NC; i++) {
        if (i + 1 < NC) {
            stage_ab(A, B, lda, ldb, arow0, brow0, (i + 1) * 32,
                     sbase + ((i + 1) & 1) * BUFB);
            asm volatile("cp.async.commit_group;");
            asm volatile("cp.async.wait_group 1;");
        } else {
            asm volatile("cp.async.wait_group 0;");
        }
        __syncthreads();
        chunk1(sbase + (i & 1) * BUFB, wm, wn, lane, c);
        __syncthreads();
    }
}

// ---------------------------------------------------------------------------
// Kernel 2: h = relu(y @ W1^T + b1) -> fp16
// ---------------------------------------------------------------------------
__global__ __launch_bounds__(256, 3) void gemm1_mma(const float* __restrict__ bias1)
{
    extern __shared__ char dsm[];
    float c[2][4][4];
    #pragma unroll
    for (int a = 0; a < 2; a++)
        #pragma unroll
        for (int b = 0; b < 4; b++)
            #pragma unroll
            for (int d = 0; d < 4; d++) c[a][b][d] = 0.f;

    const int j0 = blockIdx.x << 7;
    const int m0 = blockIdx.y << 6;

    run_gemm64<4>(g_y, g_w1h, C_DIM, C_DIM, m0, j0, s2u(dsm), c);

    const int tid = threadIdx.x;
    const int wid = tid >> 5, lane = tid & 31;
    const int wm = wid >> 2, wn = wid & 3;
    const int r = lane >> 2, q = lane & 3;

    uint32_t* dh = (uint32_t*)g_h;
    #pragma unroll
    for (int nf = 0; nf < 4; nf++) {
        const int jc = j0 + wn * 32 + nf * 8 + 2 * q;
        const float2 bb = *reinterpret_cast<const float2*>(bias1 + jc);
        #pragma unroll
        for (int mf = 0; mf < 2; mf++)
            #pragma unroll
            for (int hf = 0; hf < 2; hf++) {
                const int row = m0 + wm * 32 + mf * 16 + r + 8 * hf;
                const float v0 = fmaxf(c[mf][nf][2 * hf]     + bb.x, 0.f);
                const float v1 = fmaxf(c[mf][nf][2 * hf + 1] + bb.y, 0.f);
                dh[(size_t)row * (D_BOT / 2) + (jc >> 1)] =
                    packh(__float2half(v0), __float2half(v1));
            }
    }
}

// ---------------------------------------------------------------------------
// Kernel 3: out = x + (h @ W2^T + b2), NCHW + residual
// ---------------------------------------------------------------------------
__global__ __launch_bounds__(256, 3) void gemm2_mma(const float* __restrict__ x,
                                                    const float* __restrict__ b2,
                                                    float* __restrict__ out)
{
    extern __shared__ char dsm[];
    float c[2][4][4];
    #pragma unroll
    for (int a = 0; a < 2; a++)
        #pragma unroll
        for (int b = 0; b < 4; b++)
            #pragma unroll
            for (int d = 0; d < 4; d++) c[a][b][d] = 0.f;

    const int m0 = blockIdx.x << 6;

    run_gemm64<16>(g_h, g_w2h, D_BOT, D_BOT, m0, 0, s2u(dsm), c);

    const int tid = threadIdx.x;
    const int wid = tid >> 5, lane = tid & 31;
    const int wm = wid >> 2, wn = wid & 3;
    const int r = lane >> 2, q = lane & 3;

    float* sC = (float*)dsm;                  // 64 ch x 68 floats per half
    const int n  = m0 >> 12;
    const int sp0 = m0 & 4095;

    #pragma unroll 1
    for (int hh = 0; hh < 2; hh++) {
        if ((wn >> 1) == hh) {
            #pragma unroll
            for (int nf = 0; nf < 4; nf++) {
                const int cl = (wn & 1) * 32 + nf * 8 + 2 * q;
                #pragma unroll
                for (int mf = 0; mf < 2; mf++)
                    #pragma unroll
                    for (int hf = 0; hf < 2; hf++) {
                        const int ml = wm * 32 + mf * 16 + r + 8 * hf;
                        sC[cl * 68 + ml]       = c[mf][nf][2 * hf];
                        sC[(cl + 1) * 68 + ml] = c[mf][nf][2 * hf + 1];
                    }
            }
        }
        __syncthreads();
        #pragma unroll
        for (int qi = 0; qi < 4; qi++) {
            const int idx = qi * 256 + tid;
            const int j   = idx >> 4;          // 0..63
            const int m4  = (idx & 15) << 2;   // 0..60
            const int ch  = hh * 64 + j;
            const float bc = __ldg(&b2[ch]);
            const size_t g = ((size_t)(n * C_DIM + ch) << 12) + sp0 + m4;
            float4 v  = *reinterpret_cast<const float4*>(&sC[j * 68 + m4]);
            float4 xv = *reinterpret_cast<const float4*>(x + g);
            float4 o;
            o.x = v.x + xv.x + bc;
            o.y = v.y + xv.y + bc;
            o.z = v.z + xv.z + bc;
            o.w = v.w + xv.w + bc;
            *reinterpret_cast<float4*>(out + g) = o;
        }
        __syncthreads();
    }
}

// ---------------------------------------------------------------------------
extern "C" void kernel_launch(void* const* d_in, const int* in_sizes, int n_in,
                              void* d_out, int out_size)
{
    const float* x     = (const float*)d_in[0];
    const float* dw_w  = (const float*)d_in[1];
    const float* dw_b  = (const float*)d_in[2];
    const float* gamma = (const float*)d_in[3];
    const float* beta  = (const float*)d_in[4];
    const float* pw1_w = (const float*)d_in[5];
    const float* pw1_b = (const float*)d_in[6];
    const float* pw2_w = (const float*)d_in[7];
    const float* pw2_b = (const float*)d_in[8];
    float* out = (float*)d_out;

    static bool attr_done = false;
    if (!attr_done) {
        cudaFuncSetAttribute(dwln_kernel, cudaFuncAttributeMaxDynamicSharedMemorySize, DWLN_SMEM);
        cudaFuncSetAttribute(gemm1_mma, cudaFuncAttributeMaxDynamicSharedMemorySize, SMEM_G);
        cudaFuncSetAttribute(gemm2_mma, cudaFuncAttributeMaxDynamicSharedMemorySize, SMEM_G);
        attr_done = true;
    }

    wconv_kernel<<<(D_BOT * C_DIM + 255) / 256, 256>>>(pw1_w, pw2_w);
    dwln_kernel<<<N_IMG * H_DIM / 2, 256, DWLN_SMEM>>>(x, dw_w, dw_b, gamma, beta);
    gemm1_mma<<<dim3(D_BOT / 128, M_TOT / 64), 256, SMEM_G>>>(pw1_b);
    gemm2_mma<<<M_TOT / 64, 256, SMEM_G>>>(x, pw2_b, out);
}

// round 9
// speedup vs baseline: 1.5378x; 1.1894x over previous
#include <cuda_runtime.h>
#include <cuda_fp16.h>
#include <cstdint>

// ConvNeXt block: dwconv7x7 -> LN -> 1x1 MLP (fp16 mma.sync, 1-term) -> residual
#define N_IMG 32
#define C_DIM 128
#define H_DIM 64
#define W_DIM 64
#define D_BOT 512
#define EPS_LN 1e-5f
#define M_TOT (N_IMG * H_DIM * W_DIM)   // 131072

// ---------------- scratch (device globals; no allocs) ----------------------
__device__ __half g_y[(size_t)M_TOT * C_DIM];
__device__ __half g_h[(size_t)M_TOT * D_BOT];
__device__ __half g_w1h[D_BOT * C_DIM];
__device__ __half g_w2h[C_DIM * D_BOT];

// ---------------- helpers ---------------------------------------------------
__device__ __forceinline__ uint32_t s2u(const void* p) {
    uint32_t a;
    asm("{ .reg .u64 t; cvta.to.shared.u64 t, %1; cvt.u32.u64 %0, t; }"
        : "=r"(a) : "l"(p));
    return a;
}
__device__ __forceinline__ void cpasync16(uint32_t dst, const void* src) {
    asm volatile("cp.async.cg.shared.global [%0], [%1], 16;" :: "r"(dst), "l"(src));
}
__device__ __forceinline__ void ldsm4(uint32_t* r, uint32_t addr) {
    asm volatile("ldmatrix.sync.aligned.m8n8.x4.shared.b16 {%0,%1,%2,%3}, [%4];"
                 : "=r"(r[0]), "=r"(r[1]), "=r"(r[2]), "=r"(r[3]) : "r"(addr));
}
__device__ __forceinline__ void mma_f16(float* c, uint32_t a0, uint32_t a1,
                                        uint32_t a2, uint32_t a3,
                                        uint32_t b0, uint32_t b1) {
    asm volatile(
        "mma.sync.aligned.m16n8k16.row.col.f32.f16.f16.f32 "
        "{%0,%1,%2,%3}, {%4,%5,%6,%7}, {%8,%9}, {%0,%1,%2,%3};"
        : "+f"(c[0]), "+f"(c[1]), "+f"(c[2]), "+f"(c[3])
        : "r"(a0), "r"(a1), "r"(a2), "r"(a3), "r"(b0), "r"(b1));
}
__device__ __forceinline__ uint32_t packh(__half a, __half b) {
    return (uint32_t)__half_as_ushort(a) | ((uint32_t)__half_as_ushort(b) << 16);
}
// ---- f32x2 packed-FMA helpers ----
__device__ __forceinline__ unsigned long long splat2(float x) {
    unsigned long long r;
    unsigned int xi = __float_as_uint(x);
    asm("mov.b64 %0, {%1, %1};" : "=l"(r) : "r"(xi));
    return r;
}
__device__ __forceinline__ unsigned long long pack2(float a, float b) {
    unsigned long long r;
    asm("mov.b64 %0, {%1, %2};" : "=l"(r) : "f"(a), "f"(b));
    return r;
}
__device__ __forceinline__ void ffma2(unsigned long long& d,
                                      unsigned long long a,
                                      unsigned long long b) {
    asm("fma.rn.f32x2 %0, %1, %2, %0;" : "+l"(d) : "l"(a), "l"(b));
}
__device__ __forceinline__ float2 u2f(unsigned long long u) {
    float2 f;
    asm("mov.b64 {%0, %1}, %2;" : "=f"(f.x), "=f"(f.y) : "l"(u));
    return f;
}

// ---------------------------------------------------------------------------
// Kernel 0: weights -> fp16
// ---------------------------------------------------------------------------
__global__ __launch_bounds__(256) void wconv_kernel(const float* __restrict__ w1,
                                                    const float* __restrict__ w2) {
    int i = blockIdx.x * 256 + threadIdx.x;
    if (i < D_BOT * C_DIM) {
        g_w1h[i] = __float2half(w1[i]);
        g_w2h[i] = __float2half(w2[i]);
    }
}

// ---------------------------------------------------------------------------
// Kernel 1: dwconv 7x7 + bias + LN -> fp16 NHWC.
// CTA = (n, 2 output rows). No staging: each lane loads its 12-float window
// straight from global (L2-resident), both output rows packed in f32x2 FMAs.
// ---------------------------------------------------------------------------
#define DW_SY    (128 * 129)                 // floats
#define DWLN_SMEM (DW_SY * 4)                // 66048 B

__global__ __launch_bounds__(256, 3) void dwln_kernel(
    const float* __restrict__ x, const float* __restrict__ dw_w,
    const float* __restrict__ dw_b, const float* __restrict__ gamma,
    const float* __restrict__ beta)
{
    extern __shared__ float s_y[];      // [128 pos][129]

    const int b = blockIdx.x;
    const int n  = b >> 5;
    const int h0 = (b & 31) << 1;
    const int tid = threadIdx.x;
    const int wg = tid >> 5;
    const int l  = tid & 31;
    const int half = l >> 4;
    const int li = l & 15;

    #pragma unroll 1
    for (int it = 0; it < 8; it++) {
        const int c = wg * 16 + it * 2 + half;
        const float* wp = dw_w + c * 49;
        const float* xc = x + ((size_t)n * C_DIM + c) * (H_DIM * W_DIM);
        const float bias = __ldg(&dw_b[c]);

        unsigned long long acc[4];
        #pragma unroll
        for (int j = 0; j < 4; j++) acc[j] = splat2(bias);

        float wprev[7];
        #pragma unroll
        for (int k = 0; k < 7; k++) wprev[k] = 0.f;

        #pragma unroll
        for (int dy = 0; dy < 8; dy++) {
            const int hh = h0 - 3 + dy;
            float4 v0 = make_float4(0.f, 0.f, 0.f, 0.f);
            float4 v1 = v0, v2 = v0;
            if (hh >= 0 && hh < H_DIM) {
                const float* rp = xc + hh * W_DIM + 4 * li;
                if (li > 0)  v0 = *reinterpret_cast<const float4*>(rp - 4);
                v1 = *reinterpret_cast<const float4*>(rp);
                if (li < 15) v2 = *reinterpret_cast<const float4*>(rp + 4);
            }
            const float s[10] = {v0.y, v0.z, v0.w, v1.x, v1.y,
                                 v1.z, v1.w, v2.x, v2.y, v2.z};
            unsigned long long sp[10];
            #pragma unroll
            for (int k = 0; k < 10; k++) sp[k] = splat2(s[k]);

            float wcur[7];
            #pragma unroll
            for (int k = 0; k < 7; k++)
                wcur[k] = (dy < 7) ? __ldg(&wp[dy * 7 + k]) : 0.f;

            #pragma unroll
            for (int dx = 0; dx < 7; dx++) {
                const unsigned long long wpair = pack2(wcur[dx], wprev[dx]);
                #pragma unroll
                for (int j = 0; j < 4; j++)
                    ffma2(acc[j], sp[dx + j], wpair);
            }
            #pragma unroll
            for (int k = 0; k < 7; k++) wprev[k] = wcur[k];
        }
        #pragma unroll
        for (int j = 0; j < 4; j++) {
            const float2 f = u2f(acc[j]);
            s_y[(4 * li + j) * 129 + c]      = f.x;   // row h0
            s_y[(64 + 4 * li + j) * 129 + c] = f.y;   // row h0+1
        }
    }
    __syncthreads();

    // LayerNorm over 128 channels; warp wg handles positions wg*16..wg*16+15
    for (int wi = 0; wi < 16; wi++) {
        const int p = wg * 16 + wi;             // 0..127 (row = p>>6, w = p&63)
        float v[4], s = 0.f, sq = 0.f;
        #pragma unroll
        for (int i = 0; i < 4; i++) {
            v[i] = s_y[p * 129 + l + 32 * i];
            s += v[i];
            sq += v[i] * v[i];
        }
        #pragma unroll
        for (int o = 16; o > 0; o >>= 1) {
            s  += __shfl_xor_sync(0xffffffffu, s, o);
            sq += __shfl_xor_sync(0xffffffffu, sq, o);
        }
        const float mu  = s * (1.f / 128.f);
        const float var = sq * (1.f / 128.f) - mu * mu;
        const float rs  = rsqrtf(var + EPS_LN);
        const size_t row =
            (((size_t)n * H_DIM + h0 + (p >> 6)) * W_DIM + (p & 63)) * C_DIM;
        #pragma unroll
        for (int i = 0; i < 4; i++) {
            const int cix = l + 32 * i;
            const float val = (v[i] - mu) * rs * __ldg(&gamma[cix]) + __ldg(&beta[cix]);
            g_y[row + cix] = __float2half(val);
        }
    }
}

// ---------------------------------------------------------------------------
// mma.sync GEMM: CTA 64x128, 8 warps (2x4), warp tile 32x32, K-chunk 32.
// ---------------------------------------------------------------------------
#define ROWB 80
#define AMAT (64 * ROWB)         // 5120 B
#define BMAT (128 * ROWB)        // 10240 B
#define BUFB (AMAT + BMAT)       // 15360 B
#define SMEM_G (2 * BUFB)        // 30720 B

__device__ __forceinline__ void stage_ab(const __half* __restrict__ A,
                                         const __half* __restrict__ B,
                                         int lda, int ldb, int arow0, int brow0,
                                         int k0, uint32_t buf)
{
    const int t = threadIdx.x;
    {
        const int row = t >> 2, seg = t & 3;
        cpasync16(buf + row * ROWB + seg * 16,
                  A + (size_t)(arow0 + row) * lda + k0 + seg * 8);
    }
    #pragma unroll
    for (int p = 0; p < 2; p++) {
        const int idx = p * 256 + t;
        const int row = idx >> 2, seg = idx & 3;
        cpasync16(buf + AMAT + row * ROWB + seg * 16,
                  B + (size_t)(brow0 + row) * ldb + k0 + seg * 8);
    }
}

__device__ __forceinline__ void chunk1(uint32_t buf, int wm, int wn, int lane,
                                       float c[2][4][4])
{
    #pragma unroll
    for (int ks = 0; ks < 2; ks++) {
        const uint32_t aAddr = buf + (wm * 32 + (lane & 15)) * ROWB +
                               ks * 32 + (lane >> 4) * 16;
        const uint32_t bAddr = buf + AMAT +
                               (wn * 32 + (lane & 7) + (lane >> 4) * 8) * ROWB +
                               ks * 32 + ((lane >> 3) & 1) * 16;
        uint32_t Af[2][4], Bf[2][4];
        #pragma unroll
        for (int mf = 0; mf < 2; mf++) ldsm4(Af[mf], aAddr + mf * (16 * ROWB));
        #pragma unroll
        for (int n2 = 0; n2 < 2; n2++) ldsm4(Bf[n2], bAddr + n2 * (16 * ROWB));
        #pragma unroll
        for (int mf = 0; mf < 2; mf++)
            #pragma unroll
            for (int nf = 0; nf < 4; nf++)
                mma_f16(c[mf][nf], Af[mf][0], Af[mf][1], Af[mf][2], Af[mf][3],
                        Bf[nf >> 1][(nf & 1) * 2], Bf[nf >> 1][(nf & 1) * 2 + 1]);
    }
}

template <int NC>
__device__ __forceinline__ void run_gemm64(
    const __half* A, const __half* B, int lda, int ldb, int arow0, int brow0,
    uint32_t sbase, float c[2][4][4])
{
    const int tid = threadIdx.x;
    const int wid = tid >> 5, lane = tid & 31;
    const int wm = wid >> 2, wn = wid & 3;

    stage_ab(A, B, lda, ldb, arow0, brow0, 0, sbase);
    asm volatile("cp.async.commit_group;");

    #pragma unroll 1
    for (int i = 0; i < NC; i++) {
        if (i + 1 < NC) {
            stage_ab(A, B, lda, ldb, arow0, brow0, (i + 1) * 32,
                     sbase + ((i + 1) & 1) * BUFB);
            asm volatile("cp.async.commit_group;");
            asm volatile("cp.async.wait_group 1;");
        } else {
            asm volatile("cp.async.wait_group 0;");
        }
        __syncthreads();
        chunk1(sbase + (i & 1) * BUFB, wm, wn, lane, c);
        __syncthreads();
    }
}

// ---------------------------------------------------------------------------
// Kernel 2: h = relu(y @ W1^T + b1) -> fp16
// ---------------------------------------------------------------------------
__global__ __launch_bounds__(256, 3) void gemm1_mma(const float* __restrict__ bias1)
{
    extern __shared__ char dsm[];
    float c[2][4][4];
    #pragma unroll
    for (int a = 0; a < 2; a++)
        #pragma unroll
        for (int b = 0; b < 4; b++)
            #pragma unroll
            for (int d = 0; d < 4; d++) c[a][b][d] = 0.f;

    const int j0 = blockIdx.x << 7;
    const int m0 = blockIdx.y << 6;

    run_gemm64<4>(g_y, g_w1h, C_DIM, C_DIM, m0, j0, s2u(dsm), c);

    const int tid = threadIdx.x;
    const int wid = tid >> 5, lane = tid & 31;
    const int wm = wid >> 2, wn = wid & 3;
    const int r = lane >> 2, q = lane & 3;

    uint32_t* dh = (uint32_t*)g_h;
    #pragma unroll
    for (int nf = 0; nf < 4; nf++) {
        const int jc = j0 + wn * 32 + nf * 8 + 2 * q;
        const float2 bb = *reinterpret_cast<const float2*>(bias1 + jc);
        #pragma unroll
        for (int mf = 0; mf < 2; mf++)
            #pragma unroll
            for (int hf = 0; hf < 2; hf++) {
                const int row = m0 + wm * 32 + mf * 16 + r + 8 * hf;
                const float v0 = fmaxf(c[mf][nf][2 * hf]     + bb.x, 0.f);
                const float v1 = fmaxf(c[mf][nf][2 * hf + 1] + bb.y, 0.f);
                dh[(size_t)row * (D_BOT / 2) + (jc >> 1)] =
                    packh(__float2half(v0), __float2half(v1));
            }
    }
}

// ---------------------------------------------------------------------------
// Kernel 3: out = x + (h @ W2^T + b2), NCHW + residual
// ---------------------------------------------------------------------------
__global__ __launch_bounds__(256, 3) void gemm2_mma(const float* __restrict__ x,
                                                    const float* __restrict__ b2,
                                                    float* __restrict__ out)
{
    extern __shared__ char dsm[];
    float c[2][4][4];
    #pragma unroll
    for (int a = 0; a < 2; a++)
        #pragma unroll
        for (int b = 0; b < 4; b++)
            #pragma unroll
            for (int d = 0; d < 4; d++) c[a][b][d] = 0.f;

    const int m0 = blockIdx.x << 6;

    run_gemm64<16>(g_h, g_w2h, D_BOT, D_BOT, m0, 0, s2u(dsm), c);

    const int tid = threadIdx.x;
    const int wid = tid >> 5, lane = tid & 31;
    const int wm = wid >> 2, wn = wid & 3;
    const int r = lane >> 2, q = lane & 3;

    float* sC = (float*)dsm;                  // 64 ch x 68 floats per half
    const int n  = m0 >> 12;
    const int sp0 = m0 & 4095;

    #pragma unroll 1
    for (int hh = 0; hh < 2; hh++) {
        if ((wn >> 1) == hh) {
            #pragma unroll
            for (int nf = 0; nf < 4; nf++) {
                const int cl = (wn & 1) * 32 + nf * 8 + 2 * q;
                #pragma unroll
                for (int mf = 0; mf < 2; mf++)
                    #pragma unroll
                    for (int hf = 0; hf < 2; hf++) {
                        const int ml = wm * 32 + mf * 16 + r + 8 * hf;
                        sC[cl * 68 + ml]       = c[mf][nf][2 * hf];
                        sC[(cl + 1) * 68 + ml] = c[mf][nf][2 * hf + 1];
                    }
            }
        }
        __syncthreads();
        #pragma unroll
        for (int qi = 0; qi < 4; qi++) {
            const int idx = qi * 256 + tid;
            const int j   = idx >> 4;          // 0..63
            const int m4  = (idx & 15) << 2;   // 0..60
            const int ch  = hh * 64 + j;
            const float bc = __ldg(&b2[ch]);
            const size_t g = ((size_t)(n * C_DIM + ch) << 12) + sp0 + m4;
            float4 v  = *reinterpret_cast<const float4*>(&sC[j * 68 + m4]);
            float4 xv = *reinterpret_cast<const float4*>(x + g);
            float4 o;
            o.x = v.x + xv.x + bc;
            o.y = v.y + xv.y + bc;
            o.z = v.z + xv.z + bc;
            o.w = v.w + xv.w + bc;
            *reinterpret_cast<float4*>(out + g) = o;
        }
        __syncthreads();
    }
}

// ---------------------------------------------------------------------------
extern "C" void kernel_launch(void* const* d_in, const int* in_sizes, int n_in,
                              void* d_out, int out_size)
{
    const float* x     = (const float*)d_in[0];
    const float* dw_w  = (const float*)d_in[1];
    const float* dw_b  = (const float*)d_in[2];
    const float* gamma = (const float*)d_in[3];
    const float* beta  = (const float*)d_in[4];
    const float* pw1_w = (const float*)d_in[5];
    const float* pw1_b = (const float*)d_in[6];
    const float* pw2_w = (const float*)d_in[7];
    const float* pw2_b = (const float*)d_in[8];
    float* out = (float*)d_out;

    static bool attr_done = false;
    if (!attr_done) {
        cudaFuncSetAttribute(dwln_kernel, cudaFuncAttributeMaxDynamicSharedMemorySize, DWLN_SMEM);
        cudaFuncSetAttribute(gemm1_mma, cudaFuncAttributeMaxDynamicSharedMemorySize, SMEM_G);
        cudaFuncSetAttribute(gemm2_mma, cudaFuncAttributeMaxDynamicSharedMemorySize, SMEM_G);
        attr_done = true;
    }

    wconv_kernel<<<(D_BOT * C_DIM + 255) / 256, 256>>>(pw1_w, pw2_w);
    dwln_kernel<<<N_IMG * H_DIM / 2, 256, DWLN_SMEM>>>(x, dw_w, dw_b, gamma, beta);
    gemm1_mma<<<dim3(D_BOT / 128, M_TOT / 64), 256, SMEM_G>>>(pw1_b);
    gemm2_mma<<<M_TOT / 64, 256, SMEM_G>>>(x, pw2_b, out);
}

// round 10
// speedup vs baseline: 1.6098x; 1.0468x over previous
#include <cuda_runtime.h>
#include <cuda_fp16.h>
#include <cstdint>

// ConvNeXt block: dwconv7x7 -> LN -> 1x1 MLP (fp16 mma.sync, 1-term) -> residual
#define N_IMG 32
#define C_DIM 128
#define H_DIM 64
#define W_DIM 64
#define D_BOT 512
#define EPS_LN 1e-5f
#define M_TOT (N_IMG * H_DIM * W_DIM)   // 131072

// ---------------- scratch (device globals; no allocs) ----------------------
__device__ __half g_y[(size_t)M_TOT * C_DIM];
__device__ __half g_h[(size_t)M_TOT * D_BOT];
__device__ __half g_w1h[D_BOT * C_DIM];
__device__ __half g_w2h[C_DIM * D_BOT];

// ---------------- helpers ---------------------------------------------------
__device__ __forceinline__ uint32_t s2u(const void* p) {
    uint32_t a;
    asm("{ .reg .u64 t; cvta.to.shared.u64 t, %1; cvt.u32.u64 %0, t; }"
        : "=r"(a) : "l"(p));
    return a;
}
__device__ __forceinline__ void cpasync16(uint32_t dst, const void* src) {
    asm volatile("cp.async.cg.shared.global [%0], [%1], 16;" :: "r"(dst), "l"(src));
}
__device__ __forceinline__ void ldsm4(uint32_t* r, uint32_t addr) {
    asm volatile("ldmatrix.sync.aligned.m8n8.x4.shared.b16 {%0,%1,%2,%3}, [%4];"
                 : "=r"(r[0]), "=r"(r[1]), "=r"(r[2]), "=r"(r[3]) : "r"(addr));
}
__device__ __forceinline__ void mma_f16(float* c, uint32_t a0, uint32_t a1,
                                        uint32_t a2, uint32_t a3,
                                        uint32_t b0, uint32_t b1) {
    asm volatile(
        "mma.sync.aligned.m16n8k16.row.col.f32.f16.f16.f32 "
        "{%0,%1,%2,%3}, {%4,%5,%6,%7}, {%8,%9}, {%0,%1,%2,%3};"
        : "+f"(c[0]), "+f"(c[1]), "+f"(c[2]), "+f"(c[3])
        : "r"(a0), "r"(a1), "r"(a2), "r"(a3), "r"(b0), "r"(b1));
}
__device__ __forceinline__ uint32_t packh(__half a, __half b) {
    return (uint32_t)__half_as_ushort(a) | ((uint32_t)__half_as_ushort(b) << 16);
}
// ---- f32x2 packed-FMA helpers ----
__device__ __forceinline__ unsigned long long splat2(float x) {
    unsigned long long r;
    unsigned int xi = __float_as_uint(x);
    asm("mov.b64 %0, {%1, %1};" : "=l"(r) : "r"(xi));
    return r;
}
__device__ __forceinline__ unsigned long long pack2(float a, float b) {
    unsigned long long r;
    asm("mov.b64 %0, {%1, %2};" : "=l"(r) : "f"(a), "f"(b));
    return r;
}
__device__ __forceinline__ void ffma2(unsigned long long& d,
                                      unsigned long long a,
                                      unsigned long long b) {
    asm("fma.rn.f32x2 %0, %1, %2, %0;" : "+l"(d) : "l"(a), "l"(b));
}
__device__ __forceinline__ float2 u2f(unsigned long long u) {
    float2 f;
    asm("mov.b64 {%0, %1}, %2;" : "=f"(f.x), "=f"(f.y) : "l"(u));
    return f;
}

// ---------------------------------------------------------------------------
// Kernel 0: weights -> fp16
// ---------------------------------------------------------------------------
__global__ __launch_bounds__(256) void wconv_kernel(const float* __restrict__ w1,
                                                    const float* __restrict__ w2) {
    int i = blockIdx.x * 256 + threadIdx.x;
    if (i < D_BOT * C_DIM) {
        g_w1h[i] = __float2half(w1[i]);
        g_w2h[i] = __float2half(w2[i]);
    }
}

// ---------------------------------------------------------------------------
// Kernel 1: dwconv 7x7 + bias + LN -> fp16 NHWC.
// CTA = (n, 2 output rows). Each lane processes TWO channels (c, c+16) for
// doubled memory-level parallelism; both output rows packed in f32x2 FMAs.
// ---------------------------------------------------------------------------
#define DW_SY    (128 * 129)                 // floats
#define DWLN_SMEM (DW_SY * 4)                // 66048 B

__global__ __launch_bounds__(256, 2) void dwln_kernel(
    const float* __restrict__ x, const float* __restrict__ dw_w,
    const float* __restrict__ dw_b, const float* __restrict__ gamma,
    const float* __restrict__ beta)
{
    extern __shared__ float s_y[];      // [128 pos][129]

    const int b = blockIdx.x;
    const int n  = b >> 5;
    const int h0 = (b & 31) << 1;
    const int tid = threadIdx.x;
    const int wg = tid >> 5;
    const int l  = tid & 31;
    const int half = l >> 4;
    const int li = l & 15;
    const int slot = wg * 2 + half;

    #pragma unroll 1
    for (int it = 0; it < 4; it++) {
        const int c0 = it * 32 + slot;
        const int c1 = c0 + 16;
        const float* xc0 = x + ((size_t)n * C_DIM + c0) * (H_DIM * W_DIM);
        const float* xc1 = x + ((size_t)n * C_DIM + c1) * (H_DIM * W_DIM);
        const float* wq0 = dw_w + c0 * 49;
        const float* wq1 = dw_w + c1 * 49;

        unsigned long long acc0[4], acc1[4];
        {
            const float bi0 = __ldg(&dw_b[c0]);
            const float bi1 = __ldg(&dw_b[c1]);
            #pragma unroll
            for (int j = 0; j < 4; j++) { acc0[j] = splat2(bi0); acc1[j] = splat2(bi1); }
        }
        float wprev0[7], wprev1[7];
        #pragma unroll
        for (int k = 0; k < 7; k++) { wprev0[k] = 0.f; wprev1[k] = 0.f; }

        #pragma unroll 1
        for (int dy = 0; dy < 8; dy++) {
            const int hh = h0 - 3 + dy;
            float4 a0, a1, a2, d0, d1, d2;
            a0 = a1 = a2 = make_float4(0.f, 0.f, 0.f, 0.f);
            d0 = d1 = d2 = a0;
            if (hh >= 0 && hh < H_DIM) {
                const float* r0 = xc0 + hh * W_DIM + 4 * li;
                const float* r1 = xc1 + hh * W_DIM + 4 * li;
                if (li > 0)  { a0 = *reinterpret_cast<const float4*>(r0 - 4);
                               d0 = *reinterpret_cast<const float4*>(r1 - 4); }
                a1 = *reinterpret_cast<const float4*>(r0);
                d1 = *reinterpret_cast<const float4*>(r1);
                if (li < 15) { a2 = *reinterpret_cast<const float4*>(r0 + 4);
                               d2 = *reinterpret_cast<const float4*>(r1 + 4); }
            }
            float wcur0[7], wcur1[7];
            #pragma unroll
            for (int k = 0; k < 7; k++) {
                wcur0[k] = (dy < 7) ? __ldg(&wq0[dy * 7 + k]) : 0.f;
                wcur1[k] = (dy < 7) ? __ldg(&wq1[dy * 7 + k]) : 0.f;
            }
            const float s0[10] = {a0.y, a0.z, a0.w, a1.x, a1.y,
                                  a1.z, a1.w, a2.x, a2.y, a2.z};
            const float s1[10] = {d0.y, d0.z, d0.w, d1.x, d1.y,
                                  d1.z, d1.w, d2.x, d2.y, d2.z};
            unsigned long long sp0[10], sp1[10];
            #pragma unroll
            for (int k = 0; k < 10; k++) { sp0[k] = splat2(s0[k]); sp1[k] = splat2(s1[k]); }

            #pragma unroll
            for (int dx = 0; dx < 7; dx++) {
                const unsigned long long wpa = pack2(wcur0[dx], wprev0[dx]);
                const unsigned long long wpb = pack2(wcur1[dx], wprev1[dx]);
                #pragma unroll
                for (int j = 0; j < 4; j++) {
                    ffma2(acc0[j], sp0[dx + j], wpa);
                    ffma2(acc1[j], sp1[dx + j], wpb);
                }
            }
            #pragma unroll
            for (int k = 0; k < 7; k++) { wprev0[k] = wcur0[k]; wprev1[k] = wcur1[k]; }
        }
        #pragma unroll
        for (int j = 0; j < 4; j++) {
            const float2 f0 = u2f(acc0[j]);
            const float2 f1 = u2f(acc1[j]);
            s_y[(4 * li + j) * 129 + c0]      = f0.x;   // row h0
            s_y[(64 + 4 * li + j) * 129 + c0] = f0.y;   // row h0+1
            s_y[(4 * li + j) * 129 + c1]      = f1.x;
            s_y[(64 + 4 * li + j) * 129 + c1] = f1.y;
        }
    }
    __syncthreads();

    // LayerNorm over 128 channels; warp wg handles positions wg*16..wg*16+15
    for (int wi = 0; wi < 16; wi++) {
        const int p = wg * 16 + wi;             // 0..127 (row = p>>6, w = p&63)
        float v[4], s = 0.f, sq = 0.f;
        #pragma unroll
        for (int i = 0; i < 4; i++) {
            v[i] = s_y[p * 129 + l + 32 * i];
            s += v[i];
            sq += v[i] * v[i];
        }
        #pragma unroll
        for (int o = 16; o > 0; o >>= 1) {
            s  += __shfl_xor_sync(0xffffffffu, s, o);
            sq += __shfl_xor_sync(0xffffffffu, sq, o);
        }
        const float mu  = s * (1.f / 128.f);
        const float var = sq * (1.f / 128.f) - mu * mu;
        const float rs  = rsqrtf(var + EPS_LN);
        const size_t row =
            (((size_t)n * H_DIM + h0 + (p >> 6)) * W_DIM + (p & 63)) * C_DIM;
        #pragma unroll
        for (int i = 0; i < 4; i++) {
            const int cix = l + 32 * i;
            const float val = (v[i] - mu) * rs * __ldg(&gamma[cix]) + __ldg(&beta[cix]);
            g_y[row + cix] = __float2half(val);
        }
    }
}

// ---------------------------------------------------------------------------
// mma.sync GEMM: CTA 64x128, 8 warps (2x4), warp tile 32x32, K-chunk 32.
// 3-stage cp.async pipeline (two chunks in flight).
// ---------------------------------------------------------------------------
#define ROWB 80
#define AMAT (64 * ROWB)         // 5120 B
#define BMAT (128 * ROWB)        // 10240 B
#define BUFB (AMAT + BMAT)       // 15360 B
#define SMEM_G (3 * BUFB)        // 46080 B

__device__ __forceinline__ void stage_ab(const __half* __restrict__ A,
                                         const __half* __restrict__ B,
                                         int lda, int ldb, int arow0, int brow0,
                                         int k0, uint32_t buf)
{
    const int t = threadIdx.x;
    {
        const int row = t >> 2, seg = t & 3;
        cpasync16(buf + row * ROWB + seg * 16,
                  A + (size_t)(arow0 + row) * lda + k0 + seg * 8);
    }
    #pragma unroll
    for (int p = 0; p < 2; p++) {
        const int idx = p * 256 + t;
        const int row = idx >> 2, seg = idx & 3;
        cpasync16(buf + AMAT + row * ROWB + seg * 16,
                  B + (size_t)(brow0 + row) * ldb + k0 + seg * 8);
    }
}

__device__ __forceinline__ void chunk1(uint32_t buf, int wm, int wn, int lane,
                                       float c[2][4][4])
{
    #pragma unroll
    for (int ks = 0; ks < 2; ks++) {
        const uint32_t aAddr = buf + (wm * 32 + (lane & 15)) * ROWB +
                               ks * 32 + (lane >> 4) * 16;
        const uint32_t bAddr = buf + AMAT +
                               (wn * 32 + (lane & 7) + (lane >> 4) * 8) * ROWB +
                               ks * 32 + ((lane >> 3) & 1) * 16;
        uint32_t Af[2][4], Bf[2][4];
        #pragma unroll
        for (int mf = 0; mf < 2; mf++) ldsm4(Af[mf], aAddr + mf * (16 * ROWB));
        #pragma unroll
        for (int n2 = 0; n2 < 2; n2++) ldsm4(Bf[n2], bAddr + n2 * (16 * ROWB));
        #pragma unroll
        for (int mf = 0; mf < 2; mf++)
            #pragma unroll
            for (int nf = 0; nf < 4; nf++)
                mma_f16(c[mf][nf], Af[mf][0], Af[mf][1], Af[mf][2], Af[mf][3],
                        Bf[nf >> 1][(nf & 1) * 2], Bf[nf >> 1][(nf & 1) * 2 + 1]);
    }
}

template <int NC>
__device__ __forceinline__ void run_gemm64(
    const __half* A, const __half* B, int lda, int ldb, int arow0, int brow0,
    uint32_t sbase, float c[2][4][4])
{
    const int tid = threadIdx.x;
    const int wid = tid >> 5, lane = tid & 31;
    const int wm = wid >> 2, wn = wid & 3;

    stage_ab(A, B, lda, ldb, arow0, brow0, 0, sbase);
    asm volatile("cp.async.commit_group;");
    if (NC > 1) {
        stage_ab(A, B, lda, ldb, arow0, brow0, 32, sbase + BUFB);
        asm volatile("cp.async.commit_group;");
    }

    #pragma unroll 1
    for (int i = 0; i < NC; i++) {
        if (i + 2 < NC) {
            stage_ab(A, B, lda, ldb, arow0, brow0, (i + 2) * 32,
                     sbase + ((i + 2) % 3) * BUFB);
            asm volatile("cp.async.commit_group;");
            asm volatile("cp.async.wait_group 2;");
        } else if (i + 2 == NC) {
            asm volatile("cp.async.wait_group 1;");
        } else {
            asm volatile("cp.async.wait_group 0;");
        }
        __syncthreads();
        chunk1(sbase + (i % 3) * BUFB, wm, wn, lane, c);
        __syncthreads();
    }
}

// ---------------------------------------------------------------------------
// Kernel 2: h = relu(y @ W1^T + b1) -> fp16
// ---------------------------------------------------------------------------
__global__ __launch_bounds__(256, 3) void gemm1_mma(const float* __restrict__ bias1)
{
    extern __shared__ char dsm[];
    float c[2][4][4];
    #pragma unroll
    for (int a = 0; a < 2; a++)
        #pragma unroll
        for (int b = 0; b < 4; b++)
            #pragma unroll
            for (int d = 0; d < 4; d++) c[a][b][d] = 0.f;

    const int j0 = blockIdx.x << 7;
    const int m0 = blockIdx.y << 6;

    run_gemm64<4>(g_y, g_w1h, C_DIM, C_DIM, m0, j0, s2u(dsm), c);

    const int tid = threadIdx.x;
    const int wid = tid >> 5, lane = tid & 31;
    const int wm = wid >> 2, wn = wid & 3;
    const int r = lane >> 2, q = lane & 3;

    uint32_t* dh = (uint32_t*)g_h;
    #pragma unroll
    for (int nf = 0; nf < 4; nf++) {
        const int jc = j0 + wn * 32 + nf * 8 + 2 * q;
        const float2 bb = *reinterpret_cast<const float2*>(bias1 + jc);
        #pragma unroll
        for (int mf = 0; mf < 2; mf++)
            #pragma unroll
            for (int hf = 0; hf < 2; hf++) {
                const int row = m0 + wm * 32 + mf * 16 + r + 8 * hf;
                const float v0 = fmaxf(c[mf][nf][2 * hf]     + bb.x, 0.f);
                const float v1 = fmaxf(c[mf][nf][2 * hf + 1] + bb.y, 0.f);
                dh[(size_t)row * (D_BOT / 2) + (jc >> 1)] =
                    packh(__float2half(v0), __float2half(v1));
            }
    }
}

// ---------------------------------------------------------------------------
// Kernel 3: out = x + (h @ W2^T + b2), NCHW + residual
// ---------------------------------------------------------------------------
__global__ __launch_bounds__(256, 3) void gemm2_mma(const float* __restrict__ x,
                                                    const float* __restrict__ b2,
                                                    float* __restrict__ out)
{
    extern __shared__ char dsm[];
    float c[2][4][4];
    #pragma unroll
    for (int a = 0; a < 2; a++)
        #pragma unroll
        for (int b = 0; b < 4; b++)
            #pragma unroll
            for (int d = 0; d < 4; d++) c[a][b][d] = 0.f;

    const int m0 = blockIdx.x << 6;

    run_gemm64<16>(g_h, g_w2h, D_BOT, D_BOT, m0, 0, s2u(dsm), c);

    const int tid = threadIdx.x;
    const int wid = tid >> 5, lane = tid & 31;
    const int wm = wid >> 2, wn = wid & 3;
    const int r = lane >> 2, q = lane & 3;

    float* sC = (float*)dsm;                  // 64 ch x 68 floats per half
    const int n  = m0 >> 12;
    const int sp0 = m0 & 4095;

    #pragma unroll 1
    for (int hh = 0; hh < 2; hh++) {
        if ((wn >> 1) == hh) {
            #pragma unroll
            for (int nf = 0; nf < 4; nf++) {
                const int cl = (wn & 1) * 32 + nf * 8 + 2 * q;
                #pragma unroll
                for (int mf = 0; mf < 2; mf++)
                    #pragma unroll
                    for (int hf = 0; hf < 2; hf++) {
                        const int ml = wm * 32 + mf * 16 + r + 8 * hf;
                        sC[cl * 68 + ml]       = c[mf][nf][2 * hf];
                        sC[(cl + 1) * 68 + ml] = c[mf][nf][2 * hf + 1];
                    }
            }
        }
        __syncthreads();
        #pragma unroll
        for (int qi = 0; qi < 4; qi++) {
            const int idx = qi * 256 + tid;
            const int j   = idx >> 4;          // 0..63
            const int m4  = (idx & 15) << 2;   // 0..60
            const int ch  = hh * 64 + j;
            const float bc = __ldg(&b2[ch]);
            const size_t g = ((size_t)(n * C_DIM + ch) << 12) + sp0 + m4;
            float4 v  = *reinterpret_cast<const float4*>(&sC[j * 68 + m4]);
            float4 xv = *reinterpret_cast<const float4*>(x + g);
            float4 o;
            o.x = v.x + xv.x + bc;
            o.y = v.y + xv.y + bc;
            o.z = v.z + xv.z + bc;
            o.w = v.w + xv.w + bc;
            *reinterpret_cast<float4*>(out + g) = o;
        }
        __syncthreads();
    }
}

// ---------------------------------------------------------------------------
extern "C" void kernel_launch(void* const* d_in, const int* in_sizes, int n_in,
                              void* d_out, int out_size)
{
    const float* x     = (const float*)d_in[0];
    const float* dw_w  = (const float*)d_in[1];
    const float* dw_b  = (const float*)d_in[2];
    const float* gamma = (const float*)d_in[3];
    const float* beta  = (const float*)d_in[4];
    const float* pw1_w = (const float*)d_in[5];
    const float* pw1_b = (const float*)d_in[6];
    const float* pw2_w = (const float*)d_in[7];
    const float* pw2_b = (const float*)d_in[8];
    float* out = (float*)d_out;

    static bool attr_done = false;
    if (!attr_done) {
        cudaFuncSetAttribute(dwln_kernel, cudaFuncAttributeMaxDynamicSharedMemorySize, DWLN_SMEM);
        cudaFuncSetAttribute(gemm1_mma, cudaFuncAttributeMaxDynamicSharedMemorySize, SMEM_G);
        cudaFuncSetAttribute(gemm2_mma, cudaFuncAttributeMaxDynamicSharedMemorySize, SMEM_G);
        attr_done = true;
    }

    wconv_kernel<<<(D_BOT * C_DIM + 255) / 256, 256>>>(pw1_w, pw2_w);
    dwln_kernel<<<N_IMG * H_DIM / 2, 256, DWLN_SMEM>>>(x, dw_w, dw_b, gamma, beta);
    gemm1_mma<<<dim3(D_BOT / 128, M_TOT / 64), 256, SMEM_G>>>(pw1_b);
    gemm2_mma<<<M_TOT / 64, 256, SMEM_G>>>(x, pw2_b, out);
}

// round 11
// speedup vs baseline: 1.8664x; 1.1594x over previous
#include <cuda_runtime.h>
#include <cuda_fp16.h>
#include <cstdint>

// ConvNeXt block: dwconv7x7 -> LN -> 1x1 MLP (fp16 mma.sync, 1-term) -> residual
#define N_IMG 32
#define C_DIM 128
#define H_DIM 64
#define W_DIM 64
#define D_BOT 512
#define EPS_LN 1e-5f
#define M_TOT (N_IMG * H_DIM * W_DIM)   // 131072

// ---------------- scratch (device globals; no allocs) ----------------------
__device__ __half g_y[(size_t)M_TOT * C_DIM];
__device__ __half g_h[(size_t)M_TOT * D_BOT];
__device__ __half g_w1h[D_BOT * C_DIM];
__device__ __half g_w2h[C_DIM * D_BOT];

// ---------------- helpers ---------------------------------------------------
__device__ __forceinline__ uint32_t s2u(const void* p) {
    uint32_t a;
    asm("{ .reg .u64 t; cvta.to.shared.u64 t, %1; cvt.u32.u64 %0, t; }"
        : "=r"(a) : "l"(p));
    return a;
}
__device__ __forceinline__ void cpasync16(uint32_t dst, const void* src) {
    asm volatile("cp.async.cg.shared.global [%0], [%1], 16;" :: "r"(dst), "l"(src));
}
__device__ __forceinline__ void ldsm4(uint32_t* r, uint32_t addr) {
    asm volatile("ldmatrix.sync.aligned.m8n8.x4.shared.b16 {%0,%1,%2,%3}, [%4];"
                 : "=r"(r[0]), "=r"(r[1]), "=r"(r[2]), "=r"(r[3]) : "r"(addr));
}
__device__ __forceinline__ void mma_f16(float* c, uint32_t a0, uint32_t a1,
                                        uint32_t a2, uint32_t a3,
                                        uint32_t b0, uint32_t b1) {
    asm volatile(
        "mma.sync.aligned.m16n8k16.row.col.f32.f16.f16.f32 "
        "{%0,%1,%2,%3}, {%4,%5,%6,%7}, {%8,%9}, {%0,%1,%2,%3};"
        : "+f"(c[0]), "+f"(c[1]), "+f"(c[2]), "+f"(c[3])
        : "r"(a0), "r"(a1), "r"(a2), "r"(a3), "r"(b0), "r"(b1));
}
__device__ __forceinline__ uint32_t packh(__half a, __half b) {
    return (uint32_t)__half_as_ushort(a) | ((uint32_t)__half_as_ushort(b) << 16);
}
// ---- f32x2 packed-FMA helpers ----
__device__ __forceinline__ unsigned long long splat2(float x) {
    unsigned long long r;
    unsigned int xi = __float_as_uint(x);
    asm("mov.b64 %0, {%1, %1};" : "=l"(r) : "r"(xi));
    return r;
}
__device__ __forceinline__ unsigned long long pack2(float a, float b) {
    unsigned long long r;
    asm("mov.b64 %0, {%1, %2};" : "=l"(r) : "f"(a), "f"(b));
    return r;
}
__device__ __forceinline__ void ffma2(unsigned long long& d,
                                      unsigned long long a,
                                      unsigned long long b) {
    asm("fma.rn.f32x2 %0, %1, %2, %0;" : "+l"(d) : "l"(a), "l"(b));
}
__device__ __forceinline__ float2 u2f(unsigned long long u) {
    float2 f;
    asm("mov.b64 {%0, %1}, %2;" : "=f"(f.x), "=f"(f.y) : "l"(u));
    return f;
}

// ---------------------------------------------------------------------------
// Kernel 0: weights -> fp16
// ---------------------------------------------------------------------------
__global__ __launch_bounds__(256) void wconv_kernel(const float* __restrict__ w1,
                                                    const float* __restrict__ w2) {
    int i = blockIdx.x * 256 + threadIdx.x;
    if (i < D_BOT * C_DIM) {
        g_w1h[i] = __float2half(w1[i]);
        g_w2h[i] = __float2half(w2[i]);
    }
}

// ---------------------------------------------------------------------------
// Kernel 1: dwconv 7x7 + bias + LN -> fp16 NHWC.
// CTA = (n, 2 output rows). Lane loads ONE float4 per row per channel;
// neighbor window floats come via warp shuffle. Two channels per lane for MLP,
// FMA blocks sequential per channel to cap live registers.
// ---------------------------------------------------------------------------
#define DW_SY    (128 * 129)                 // floats
#define DWLN_SMEM (DW_SY * 4)                // 66048 B

__device__ __forceinline__ void dw_accum(
    const float4 v1, const float* wcur, const float* wprev,
    int l, int li, unsigned long long acc[4])
{
    float by = __shfl_sync(0xffffffffu, v1.y, (l - 1) & 31);
    float bz = __shfl_sync(0xffffffffu, v1.z, (l - 1) & 31);
    float bw = __shfl_sync(0xffffffffu, v1.w, (l - 1) & 31);
    float cx = __shfl_sync(0xffffffffu, v1.x, (l + 1) & 31);
    float cy = __shfl_sync(0xffffffffu, v1.y, (l + 1) & 31);
    float cz = __shfl_sync(0xffffffffu, v1.z, (l + 1) & 31);
    if (li == 0)  { by = 0.f; bz = 0.f; bw = 0.f; }
    if (li == 15) { cx = 0.f; cy = 0.f; cz = 0.f; }
    const float s[10] = {by, bz, bw, v1.x, v1.y, v1.z, v1.w, cx, cy, cz};
    unsigned long long sp[10];
    #pragma unroll
    for (int k = 0; k < 10; k++) sp[k] = splat2(s[k]);
    #pragma unroll
    for (int dx = 0; dx < 7; dx++) {
        const unsigned long long wp = pack2(wcur[dx], wprev[dx]);
        #pragma unroll
        for (int j = 0; j < 4; j++) ffma2(acc[j], sp[dx + j], wp);
    }
}

__global__ __launch_bounds__(256, 3) void dwln_kernel(
    const float* __restrict__ x, const float* __restrict__ dw_w,
    const float* __restrict__ dw_b, const float* __restrict__ gamma,
    const float* __restrict__ beta)
{
    extern __shared__ float s_y[];      // [128 pos][129]

    const int b = blockIdx.x;
    const int n  = b >> 5;
    const int h0 = (b & 31) << 1;
    const int tid = threadIdx.x;
    const int wg = tid >> 5;
    const int l  = tid & 31;
    const int half = l >> 4;
    const int li = l & 15;
    const int slot = wg * 2 + half;

    #pragma unroll 1
    for (int it = 0; it < 4; it++) {
        const int c0 = it * 32 + slot;
        const int c1 = c0 + 16;
        const float* xc0 = x + ((size_t)n * C_DIM + c0) * (H_DIM * W_DIM);
        const float* xc1 = x + ((size_t)n * C_DIM + c1) * (H_DIM * W_DIM);
        const float* wq0 = dw_w + c0 * 49;
        const float* wq1 = dw_w + c1 * 49;

        unsigned long long acc0[4], acc1[4];
        {
            const float bi0 = __ldg(&dw_b[c0]);
            const float bi1 = __ldg(&dw_b[c1]);
            #pragma unroll
            for (int j = 0; j < 4; j++) { acc0[j] = splat2(bi0); acc1[j] = splat2(bi1); }
        }
        float wprev0[7], wprev1[7];
        #pragma unroll
        for (int k = 0; k < 7; k++) { wprev0[k] = 0.f; wprev1[k] = 0.f; }

        #pragma unroll 1
        for (int dy = 0; dy < 8; dy++) {
            const int hh = h0 - 3 + dy;
            float4 v1a = make_float4(0.f, 0.f, 0.f, 0.f);
            float4 v1b = v1a;
            if (hh >= 0 && hh < H_DIM) {
                v1a = *reinterpret_cast<const float4*>(xc0 + hh * W_DIM + 4 * li);
                v1b = *reinterpret_cast<const float4*>(xc1 + hh * W_DIM + 4 * li);
            }
            float wcur0[7], wcur1[7];
            #pragma unroll
            for (int k = 0; k < 7; k++) {
                wcur0[k] = (dy < 7) ? __ldg(&wq0[dy * 7 + k]) : 0.f;
                wcur1[k] = (dy < 7) ? __ldg(&wq1[dy * 7 + k]) : 0.f;
            }
            dw_accum(v1a, wcur0, wprev0, l, li, acc0);
            dw_accum(v1b, wcur1, wprev1, l, li, acc1);
            #pragma unroll
            for (int k = 0; k < 7; k++) { wprev0[k] = wcur0[k]; wprev1[k] = wcur1[k]; }
        }
        #pragma unroll
        for (int j = 0; j < 4; j++) {
            const float2 f0 = u2f(acc0[j]);
            const float2 f1 = u2f(acc1[j]);
            s_y[(4 * li + j) * 129 + c0]      = f0.x;   // row h0
            s_y[(64 + 4 * li + j) * 129 + c0] = f0.y;   // row h0+1
            s_y[(4 * li + j) * 129 + c1]      = f1.x;
            s_y[(64 + 4 * li + j) * 129 + c1] = f1.y;
        }
    }
    __syncthreads();

    // LayerNorm over 128 channels; warp wg handles positions wg*16..wg*16+15
    for (int wi = 0; wi < 16; wi++) {
        const int p = wg * 16 + wi;             // 0..127 (row = p>>6, w = p&63)
        float v[4], s = 0.f, sq = 0.f;
        #pragma unroll
        for (int i = 0; i < 4; i++) {
            v[i] = s_y[p * 129 + l + 32 * i];
            s += v[i];
            sq += v[i] * v[i];
        }
        #pragma unroll
        for (int o = 16; o > 0; o >>= 1) {
            s  += __shfl_xor_sync(0xffffffffu, s, o);
            sq += __shfl_xor_sync(0xffffffffu, sq, o);
        }
        const float mu  = s * (1.f / 128.f);
        const float var = sq * (1.f / 128.f) - mu * mu;
        const float rs  = rsqrtf(var + EPS_LN);
        const size_t row =
            (((size_t)n * H_DIM + h0 + (p >> 6)) * W_DIM + (p & 63)) * C_DIM;
        #pragma unroll
        for (int i = 0; i < 4; i++) {
            const int cix = l + 32 * i;
            const float val = (v[i] - mu) * rs * __ldg(&gamma[cix]) + __ldg(&beta[cix]);
            g_y[row + cix] = __float2half(val);
        }
    }
}

// ---------------------------------------------------------------------------
// mma.sync GEMM: CTA 64x128, 8 warps (2x4), warp tile 32x32, K-chunk 64.
// 2-stage cp.async pipeline; ROWB=144 (128B data + 16B pad, conflict-free).
// ---------------------------------------------------------------------------
#define ROWB 144
#define AMAT (64 * ROWB)         // 9216 B
#define BMAT (128 * ROWB)        // 18432 B
#define BUFB (AMAT + BMAT)       // 27648 B
#define SMEM_G (2 * BUFB)        // 55296 B

__device__ __forceinline__ void stage_ab(const __half* __restrict__ A,
                                         const __half* __restrict__ B,
                                         int lda, int ldb, int arow0, int brow0,
                                         int k0, uint32_t buf)
{
    const int t = threadIdx.x;
    #pragma unroll
    for (int p = 0; p < 2; p++) {        // A: 64 rows x 8 segs = 512 slots
        const int idx = p * 256 + t;
        const int row = idx >> 3, seg = idx & 7;
        cpasync16(buf + row * ROWB + seg * 16,
                  A + (size_t)(arow0 + row) * lda + k0 + seg * 8);
    }
    #pragma unroll
    for (int p = 0; p < 4; p++) {        // B: 128 rows x 8 segs = 1024 slots
        const int idx = p * 256 + t;
        const int row = idx >> 3, seg = idx & 7;
        cpasync16(buf + AMAT + row * ROWB + seg * 16,
                  B + (size_t)(brow0 + row) * ldb + k0 + seg * 8);
    }
}

__device__ __forceinline__ void chunk1(uint32_t buf, int wm, int wn, int lane,
                                       float c[2][4][4])
{
    #pragma unroll
    for (int ks = 0; ks < 4; ks++) {
        const uint32_t aAddr = buf + (wm * 32 + (lane & 15)) * ROWB +
                               ks * 32 + (lane >> 4) * 16;
        const uint32_t bAddr = buf + AMAT +
                               (wn * 32 + (lane & 7) + (lane >> 4) * 8) * ROWB +
                               ks * 32 + ((lane >> 3) & 1) * 16;
        uint32_t Af[2][4], Bf[2][4];
        #pragma unroll
        for (int mf = 0; mf < 2; mf++) ldsm4(Af[mf], aAddr + mf * (16 * ROWB));
        #pragma unroll
        for (int n2 = 0; n2 < 2; n2++) ldsm4(Bf[n2], bAddr + n2 * (16 * ROWB));
        #pragma unroll
        for (int mf = 0; mf < 2; mf++)
            #pragma unroll
            for (int nf = 0; nf < 4; nf++)
                mma_f16(c[mf][nf], Af[mf][0], Af[mf][1], Af[mf][2], Af[mf][3],
                        Bf[nf >> 1][(nf & 1) * 2], Bf[nf >> 1][(nf & 1) * 2 + 1]);
    }
}

template <int NC>
__device__ __forceinline__ void run_gemm64(
    const __half* A, const __half* B, int lda, int ldb, int arow0, int brow0,
    uint32_t sbase, float c[2][4][4])
{
    const int tid = threadIdx.x;
    const int wid = tid >> 5, lane = tid & 31;
    const int wm = wid >> 2, wn = wid & 3;

    stage_ab(A, B, lda, ldb, arow0, brow0, 0, sbase);
    asm volatile("cp.async.commit_group;");

    #pragma unroll 1
    for (int i = 0; i < NC; i++) {
        if (i + 1 < NC) {
            stage_ab(A, B, lda, ldb, arow0, brow0, (i + 1) * 64,
                     sbase + ((i + 1) & 1) * BUFB);
            asm volatile("cp.async.commit_group;");
            asm volatile("cp.async.wait_group 1;");
        } else {
            asm volatile("cp.async.wait_group 0;");
        }
        __syncthreads();
        chunk1(sbase + (i & 1) * BUFB, wm, wn, lane, c);
        __syncthreads();
    }
}

// ---------------------------------------------------------------------------
// Kernel 2: h = relu(y @ W1^T + b1) -> fp16
// ---------------------------------------------------------------------------
__global__ __launch_bounds__(256, 3) void gemm1_mma(const float* __restrict__ bias1)
{
    extern __shared__ char dsm[];
    float c[2][4][4];
    #pragma unroll
    for (int a = 0; a < 2; a++)
        #pragma unroll
        for (int b = 0; b < 4; b++)
            #pragma unroll
            for (int d = 0; d < 4; d++) c[a][b][d] = 0.f;

    const int j0 = blockIdx.x << 7;
    const int m0 = blockIdx.y << 6;

    run_gemm64<2>(g_y, g_w1h, C_DIM, C_DIM, m0, j0, s2u(dsm), c);

    const int tid = threadIdx.x;
    const int wid = tid >> 5, lane = tid & 31;
    const int wm = wid >> 2, wn = wid & 3;
    const int r = lane >> 2, q = lane & 3;

    uint32_t* dh = (uint32_t*)g_h;
    #pragma unroll
    for (int nf = 0; nf < 4; nf++) {
        const int jc = j0 + wn * 32 + nf * 8 + 2 * q;
        const float2 bb = *reinterpret_cast<const float2*>(bias1 + jc);
        #pragma unroll
        for (int mf = 0; mf < 2; mf++)
            #pragma unroll
            for (int hf = 0; hf < 2; hf++) {
                const int row = m0 + wm * 32 + mf * 16 + r + 8 * hf;
                const float v0 = fmaxf(c[mf][nf][2 * hf]     + bb.x, 0.f);
                const float v1 = fmaxf(c[mf][nf][2 * hf + 1] + bb.y, 0.f);
                dh[(size_t)row * (D_BOT / 2) + (jc >> 1)] =
                    packh(__float2half(v0), __float2half(v1));
            }
    }
}

// ---------------------------------------------------------------------------
// Kernel 3: out = x + (h @ W2^T + b2), NCHW + residual
// ---------------------------------------------------------------------------
__global__ __launch_bounds__(256, 3) void gemm2_mma(const float* __restrict__ x,
                                                    const float* __restrict__ b2,
                                                    float* __restrict__ out)
{
    extern __shared__ char dsm[];
    float c[2][4][4];
    #pragma unroll
    for (int a = 0; a < 2; a++)
        #pragma unroll
        for (int b = 0; b < 4; b++)
            #pragma unroll
            for (int d = 0; d < 4; d++) c[a][b][d] = 0.f;

    const int m0 = blockIdx.x << 6;

    run_gemm64<8>(g_h, g_w2h, D_BOT, D_BOT, m0, 0, s2u(dsm), c);

    const int tid = threadIdx.x;
    const int wid = tid >> 5, lane = tid & 31;
    const int wm = wid >> 2, wn = wid & 3;
    const int r = lane >> 2, q = lane & 3;

    float* sC = (float*)dsm;                  // 64 ch x 68 floats per half
    const int n  = m0 >> 12;
    const int sp0 = m0 & 4095;

    #pragma unroll 1
    for (int hh = 0; hh < 2; hh++) {
        if ((wn >> 1) == hh) {
            #pragma unroll
            for (int nf = 0; nf < 4; nf++) {
                const int cl = (wn & 1) * 32 + nf * 8 + 2 * q;
                #pragma unroll
                for (int mf = 0; mf < 2; mf++)
                    #pragma unroll
                    for (int hf = 0; hf < 2; hf++) {
                        const int ml = wm * 32 + mf * 16 + r + 8 * hf;
                        sC[cl * 68 + ml]       = c[mf][nf][2 * hf];
                        sC[(cl + 1) * 68 + ml] = c[mf][nf][2 * hf + 1];
                    }
            }
        }
        __syncthreads();
        #pragma unroll
        for (int qi = 0; qi < 4; qi++) {
            const int idx = qi * 256 + tid;
            const int j   = idx >> 4;          // 0..63
            const int m4  = (idx & 15) << 2;   // 0..60
            const int ch  = hh * 64 + j;
            const float bc = __ldg(&b2[ch]);
            const size_t g = ((size_t)(n * C_DIM + ch) << 12) + sp0 + m4;
            float4 v  = *reinterpret_cast<const float4*>(&sC[j * 68 + m4]);
            float4 xv = *reinterpret_cast<const float4*>(x + g);
            float4 o;
            o.x = v.x + xv.x + bc;
            o.y = v.y + xv.y + bc;
            o.z = v.z + xv.z + bc;
            o.w = v.w + xv.w + bc;
            *reinterpret_cast<float4*>(out + g) = o;
        }
        __syncthreads();
    }
}

// ---------------------------------------------------------------------------
extern "C" void kernel_launch(void* const* d_in, const int* in_sizes, int n_in,
                              void* d_out, int out_size)
{
    const float* x     = (const float*)d_in[0];
    const float* dw_w  = (const float*)d_in[1];
    const float* dw_b  = (const float*)d_in[2];
    const float* gamma = (const float*)d_in[3];
    const float* beta  = (const float*)d_in[4];
    const float* pw1_w = (const float*)d_in[5];
    const float* pw1_b = (const float*)d_in[6];
    const float* pw2_w = (const float*)d_in[7];
    const float* pw2_b = (const float*)d_in[8];
    float* out = (float*)d_out;

    static bool attr_done = false;
    if (!attr_done) {
        cudaFuncSetAttribute(dwln_kernel, cudaFuncAttributeMaxDynamicSharedMemorySize, DWLN_SMEM);
        cudaFuncSetAttribute(gemm1_mma, cudaFuncAttributeMaxDynamicSharedMemorySize, SMEM_G);
        cudaFuncSetAttribute(gemm2_mma, cudaFuncAttributeMaxDynamicSharedMemorySize, SMEM_G);
        attr_done = true;
    }

    wconv_kernel<<<(D_BOT * C_DIM + 255) / 256, 256>>>(pw1_w, pw2_w);
    dwln_kernel<<<N_IMG * H_DIM / 2, 256, DWLN_SMEM>>>(x, dw_w, dw_b, gamma, beta);
    gemm1_mma<<<dim3(D_BOT / 128, M_TOT / 64), 256, SMEM_G>>>(pw1_b);
    gemm2_mma<<<M_TOT / 64, 256, SMEM_G>>>(x, pw2_b, out);
}

// round 12
// speedup vs baseline: 2.0223x; 1.0835x over previous
#include <cuda_runtime.h>
#include <cuda_fp16.h>
#include <cstdint>

// ConvNeXt block: dwconv7x7 -> LN -> fused 1x1 MLP (fp16 mma.sync) -> residual
#define N_IMG 32
#define C_DIM 128
#define H_DIM 64
#define W_DIM 64
#define D_BOT 512
#define EPS_LN 1e-5f
#define M_TOT (N_IMG * H_DIM * W_DIM)   // 131072

// ---------------- scratch (device globals; no allocs) ----------------------
__device__ __half g_y[(size_t)M_TOT * C_DIM];
__device__ __half g_w1h[D_BOT * C_DIM];
__device__ __half g_w2h[C_DIM * D_BOT];

// ---------------- helpers ---------------------------------------------------
__device__ __forceinline__ uint32_t s2u(const void* p) {
    uint32_t a;
    asm("{ .reg .u64 t; cvta.to.shared.u64 t, %1; cvt.u32.u64 %0, t; }"
        : "=r"(a) : "l"(p));
    return a;
}
__device__ __forceinline__ void cpasync16(uint32_t dst, const void* src) {
    asm volatile("cp.async.cg.shared.global [%0], [%1], 16;" :: "r"(dst), "l"(src));
}
__device__ __forceinline__ void ldsm4(uint32_t* r, uint32_t addr) {
    asm volatile("ldmatrix.sync.aligned.m8n8.x4.shared.b16 {%0,%1,%2,%3}, [%4];"
                 : "=r"(r[0]), "=r"(r[1]), "=r"(r[2]), "=r"(r[3]) : "r"(addr));
}
__device__ __forceinline__ void mma_f16(float* c, uint32_t a0, uint32_t a1,
                                        uint32_t a2, uint32_t a3,
                                        uint32_t b0, uint32_t b1) {
    asm volatile(
        "mma.sync.aligned.m16n8k16.row.col.f32.f16.f16.f32 "
        "{%0,%1,%2,%3}, {%4,%5,%6,%7}, {%8,%9}, {%0,%1,%2,%3};"
        : "+f"(c[0]), "+f"(c[1]), "+f"(c[2]), "+f"(c[3])
        : "r"(a0), "r"(a1), "r"(a2), "r"(a3), "r"(b0), "r"(b1));
}
__device__ __forceinline__ uint32_t packh(__half a, __half b) {
    return (uint32_t)__half_as_ushort(a) | ((uint32_t)__half_as_ushort(b) << 16);
}
// ---- f32x2 packed-FMA helpers ----
__device__ __forceinline__ unsigned long long splat2(float x) {
    unsigned long long r;
    unsigned int xi = __float_as_uint(x);
    asm("mov.b64 %0, {%1, %1};" : "=l"(r) : "r"(xi));
    return r;
}
__device__ __forceinline__ unsigned long long pack2(float a, float b) {
    unsigned long long r;
    asm("mov.b64 %0, {%1, %2};" : "=l"(r) : "f"(a), "f"(b));
    return r;
}
__device__ __forceinline__ void ffma2(unsigned long long& d,
                                      unsigned long long a,
                                      unsigned long long b) {
    asm("fma.rn.f32x2 %0, %1, %2, %0;" : "+l"(d) : "l"(a), "l"(b));
}
__device__ __forceinline__ float2 u2f(unsigned long long u) {
    float2 f;
    asm("mov.b64 {%0, %1}, %2;" : "=f"(f.x), "=f"(f.y) : "l"(u));
    return f;
}

// ---------------------------------------------------------------------------
// Kernel 0: weights -> fp16
// ---------------------------------------------------------------------------
__global__ __launch_bounds__(256) void wconv_kernel(const float* __restrict__ w1,
                                                    const float* __restrict__ w2) {
    int i = blockIdx.x * 256 + threadIdx.x;
    if (i < D_BOT * C_DIM) {
        g_w1h[i] = __float2half(w1[i]);
        g_w2h[i] = __float2half(w2[i]);
    }
}

// ---------------------------------------------------------------------------
// Kernel 1: dwconv 7x7 + bias + LN -> fp16 NHWC. (unchanged from R11)
// ---------------------------------------------------------------------------
#define DW_SY    (128 * 129)                 // floats
#define DWLN_SMEM (DW_SY * 4)                // 66048 B

__device__ __forceinline__ void dw_accum(
    const float4 v1, const float* wcur, const float* wprev,
    int l, int li, unsigned long long acc[4])
{
    float by = __shfl_sync(0xffffffffu, v1.y, (l - 1) & 31);
    float bz = __shfl_sync(0xffffffffu, v1.z, (l - 1) & 31);
    float bw = __shfl_sync(0xffffffffu, v1.w, (l - 1) & 31);
    float cx = __shfl_sync(0xffffffffu, v1.x, (l + 1) & 31);
    float cy = __shfl_sync(0xffffffffu, v1.y, (l + 1) & 31);
    float cz = __shfl_sync(0xffffffffu, v1.z, (l + 1) & 31);
    if (li == 0)  { by = 0.f; bz = 0.f; bw = 0.f; }
    if (li == 15) { cx = 0.f; cy = 0.f; cz = 0.f; }
    const float s[10] = {by, bz, bw, v1.x, v1.y, v1.z, v1.w, cx, cy, cz};
    unsigned long long sp[10];
    #pragma unroll
    for (int k = 0; k < 10; k++) sp[k] = splat2(s[k]);
    #pragma unroll
    for (int dx = 0; dx < 7; dx++) {
        const unsigned long long wp = pack2(wcur[dx], wprev[dx]);
        #pragma unroll
        for (int j = 0; j < 4; j++) ffma2(acc[j], sp[dx + j], wp);
    }
}

__global__ __launch_bounds__(256, 3) void dwln_kernel(
    const float* __restrict__ x, const float* __restrict__ dw_w,
    const float* __restrict__ dw_b, const float* __restrict__ gamma,
    const float* __restrict__ beta)
{
    extern __shared__ float s_y[];      // [128 pos][129]

    const int b = blockIdx.x;
    const int n  = b >> 5;
    const int h0 = (b & 31) << 1;
    const int tid = threadIdx.x;
    const int wg = tid >> 5;
    const int l  = tid & 31;
    const int half = l >> 4;
    const int li = l & 15;
    const int slot = wg * 2 + half;

    #pragma unroll 1
    for (int it = 0; it < 4; it++) {
        const int c0 = it * 32 + slot;
        const int c1 = c0 + 16;
        const float* xc0 = x + ((size_t)n * C_DIM + c0) * (H_DIM * W_DIM);
        const float* xc1 = x + ((size_t)n * C_DIM + c1) * (H_DIM * W_DIM);
        const float* wq0 = dw_w + c0 * 49;
        const float* wq1 = dw_w + c1 * 49;

        unsigned long long acc0[4], acc1[4];
        {
            const float bi0 = __ldg(&dw_b[c0]);
            const float bi1 = __ldg(&dw_b[c1]);
            #pragma unroll
            for (int j = 0; j < 4; j++) { acc0[j] = splat2(bi0); acc1[j] = splat2(bi1); }
        }
        float wprev0[7], wprev1[7];
        #pragma unroll
        for (int k = 0; k < 7; k++) { wprev0[k] = 0.f; wprev1[k] = 0.f; }

        #pragma unroll 1
        for (int dy = 0; dy < 8; dy++) {
            const int hh = h0 - 3 + dy;
            float4 v1a = make_float4(0.f, 0.f, 0.f, 0.f);
            float4 v1b = v1a;
            if (hh >= 0 && hh < H_DIM) {
                v1a = *reinterpret_cast<const float4*>(xc0 + hh * W_DIM + 4 * li);
                v1b = *reinterpret_cast<const float4*>(xc1 + hh * W_DIM + 4 * li);
            }
            float wcur0[7], wcur1[7];
            #pragma unroll
            for (int k = 0; k < 7; k++) {
                wcur0[k] = (dy < 7) ? __ldg(&wq0[dy * 7 + k]) : 0.f;
                wcur1[k] = (dy < 7) ? __ldg(&wq1[dy * 7 + k]) : 0.f;
            }
            dw_accum(v1a, wcur0, wprev0, l, li, acc0);
            dw_accum(v1b, wcur1, wprev1, l, li, acc1);
            #pragma unroll
            for (int k = 0; k < 7; k++) { wprev0[k] = wcur0[k]; wprev1[k] = wcur1[k]; }
        }
        #pragma unroll
        for (int j = 0; j < 4; j++) {
            const float2 f0 = u2f(acc0[j]);
            const float2 f1 = u2f(acc1[j]);
            s_y[(4 * li + j) * 129 + c0]      = f0.x;
            s_y[(64 + 4 * li + j) * 129 + c0] = f0.y;
            s_y[(4 * li + j) * 129 + c1]      = f1.x;
            s_y[(64 + 4 * li + j) * 129 + c1] = f1.y;
        }
    }
    __syncthreads();

    for (int wi = 0; wi < 16; wi++) {
        const int p = wg * 16 + wi;
        float v[4], s = 0.f, sq = 0.f;
        #pragma unroll
        for (int i = 0; i < 4; i++) {
            v[i] = s_y[p * 129 + l + 32 * i];
            s += v[i];
            sq += v[i] * v[i];
        }
        #pragma unroll
        for (int o = 16; o > 0; o >>= 1) {
            s  += __shfl_xor_sync(0xffffffffu, s, o);
            sq += __shfl_xor_sync(0xffffffffu, sq, o);
        }
        const float mu  = s * (1.f / 128.f);
        const float var = sq * (1.f / 128.f) - mu * mu;
        const float rs  = rsqrtf(var + EPS_LN);
        const size_t row =
            (((size_t)n * H_DIM + h0 + (p >> 6)) * W_DIM + (p & 63)) * C_DIM;
        #pragma unroll
        for (int i = 0; i < 4; i++) {
            const int cix = l + 32 * i;
            const float val = (v[i] - mu) * rs * __ldg(&gamma[cix]) + __ldg(&beta[cix]);
            g_y[row + cix] = __float2half(val);
        }
    }
}

// ---------------------------------------------------------------------------
// Fused MLP: CTA = 64 m-rows. 4 rounds over hidden chunks of 128:
//   gemm1 (K=128, 2 chunks) -> h fp16 in swizzled smem -> gemm2 partial (2 chunks).
// Uniform 16-phase cp.async pipeline across both roles; 2 CTAs/SM.
// smem: [0, 55296) staging (2 x 27648), [55296, 71680) h tile 64x128 fp16.
// ---------------------------------------------------------------------------
#define ROWB 144
#define AMAT (64 * ROWB)         // 9216 B
#define BMAT (128 * ROWB)        // 18432 B
#define BUFB (AMAT + BMAT)       // 27648 B
#define H_OFF (2 * BUFB)         // 55296
#define SMEM_F (H_OFF + 64 * 256)   // 71680

// stage A(y)+B(W1) for gemm1 phase, or B(W2) only for gemm2 phase
__device__ __forceinline__ void stage_phase(int t, int m0, uint32_t buf) {
    const int tid = threadIdx.x;
    const int jc = t >> 2, s = t & 3;
    if (s < 2) {
        const int k0 = s * 64;
        #pragma unroll
        for (int p = 0; p < 2; p++) {
            const int idx = p * 256 + tid;
            const int row = idx >> 3, seg = idx & 7;
            cpasync16(buf + row * ROWB + seg * 16,
                      g_y + (size_t)(m0 + row) * C_DIM + k0 + seg * 8);
        }
        #pragma unroll
        for (int p = 0; p < 4; p++) {
            const int idx = p * 256 + tid;
            const int row = idx >> 3, seg = idx & 7;
            cpasync16(buf + AMAT + row * ROWB + seg * 16,
                      g_w1h + (size_t)(jc * 128 + row) * C_DIM + k0 + seg * 8);
        }
    } else {
        const int k0 = jc * 128 + (s - 2) * 64;
        #pragma unroll
        for (int p = 0; p < 4; p++) {
            const int idx = p * 256 + tid;
            const int row = idx >> 3, seg = idx & 7;
            cpasync16(buf + AMAT + row * ROWB + seg * 16,
                      g_w2h + (size_t)row * D_BOT + k0 + seg * 8);
        }
    }
}

// gemm1 compute: A from staged buf, B from staged buf (identical to R11 chunk1)
__device__ __forceinline__ void chunk1(uint32_t buf, int wm, int wn, int lane,
                                       float c[2][4][4])
{
    #pragma unroll
    for (int ks = 0; ks < 4; ks++) {
        const uint32_t aAddr = buf + (wm * 32 + (lane & 15)) * ROWB +
                               ks * 32 + (lane >> 4) * 16;
        const uint32_t bAddr = buf + AMAT +
                               (wn * 32 + (lane & 7) + (lane >> 4) * 8) * ROWB +
                               ks * 32 + ((lane >> 3) & 1) * 16;
        uint32_t Af[2][4], Bf[2][4];
        #pragma unroll
        for (int mf = 0; mf < 2; mf++) ldsm4(Af[mf], aAddr + mf * (16 * ROWB));
        #pragma unroll
        for (int n2 = 0; n2 < 2; n2++) ldsm4(Bf[n2], bAddr + n2 * (16 * ROWB));
        #pragma unroll
        for (int mf = 0; mf < 2; mf++)
            #pragma unroll
            for (int nf = 0; nf < 4; nf++)
                mma_f16(c[mf][nf], Af[mf][0], Af[mf][1], Af[mf][2], Af[mf][3],
                        Bf[nf >> 1][(nf & 1) * 2], Bf[nf >> 1][(nf & 1) * 2 + 1]);
    }
}

// gemm2 compute: A from swizzled h smem (row stride 256B), B from staged buf
__device__ __forceinline__ void chunk2h(uint32_t buf, uint32_t hb, int kc,
                                        int wm, int wn, int lane, float c[2][4][4])
{
    #pragma unroll
    for (int ks = 0; ks < 4; ks++) {
        const int blk = kc * 8 + ks * 2 + (lane >> 4);
        const uint32_t aAddr0 = hb + (wm * 32 + (lane & 15)) * 256 +
                                (uint32_t)((blk ^ (lane & 7)) << 4);
        const uint32_t bAddr = buf + AMAT +
                               (wn * 32 + (lane & 7) + (lane >> 4) * 8) * ROWB +
                               ks * 32 + ((lane >> 3) & 1) * 16;
        uint32_t Af[2][4], Bf[2][4];
        #pragma unroll
        for (int mf = 0; mf < 2; mf++) ldsm4(Af[mf], aAddr0 + mf * (16 * 256));
        #pragma unroll
        for (int n2 = 0; n2 < 2; n2++) ldsm4(Bf[n2], bAddr + n2 * (16 * ROWB));
        #pragma unroll
        for (int mf = 0; mf < 2; mf++)
            #pragma unroll
            for (int nf = 0; nf < 4; nf++)
                mma_f16(c[mf][nf], Af[mf][0], Af[mf][1], Af[mf][2], Af[mf][3],
                        Bf[nf >> 1][(nf & 1) * 2], Bf[nf >> 1][(nf & 1) * 2 + 1]);
    }
}

__global__ __launch_bounds__(256, 2) void fused_mlp(
    const float* __restrict__ x, const float* __restrict__ b1,
    const float* __restrict__ b2, float* __restrict__ out)
{
    extern __shared__ char dsm[];
    const uint32_t sb = s2u(dsm);
    const uint32_t hb = sb + H_OFF;

    const int tid = threadIdx.x;
    const int wid = tid >> 5, lane = tid & 31;
    const int wm = wid >> 2, wn = wid & 3;
    const int r = lane >> 2, q = lane & 3;
    const int m0 = blockIdx.x << 6;

    float c1[2][4][4], c2[2][4][4];
    #pragma unroll
    for (int a = 0; a < 2; a++)
        #pragma unroll
        for (int b_ = 0; b_ < 4; b_++)
            #pragma unroll
            for (int d = 0; d < 4; d++) { c1[a][b_][d] = 0.f; c2[a][b_][d] = 0.f; }

    stage_phase(0, m0, sb);
    asm volatile("cp.async.commit_group;");

    #pragma unroll 1
    for (int t = 0; t < 16; t++) {
        if (t + 1 < 16) {
            stage_phase(t + 1, m0, sb + ((t + 1) & 1) * BUFB);
            asm volatile("cp.async.commit_group;");
            asm volatile("cp.async.wait_group 1;");
        } else {
            asm volatile("cp.async.wait_group 0;");
        }
        __syncthreads();
        const uint32_t buf = sb + (t & 1) * BUFB;
        const int jc = t >> 2, s = t & 3;
        if (s < 2) {
            chunk1(buf, wm, wn, lane, c1);
            if (s == 1) {
                // h epilogue: bias + relu -> fp16 into swizzled h smem
                #pragma unroll
                for (int nf = 0; nf < 4; nf++) {
                    const int col = wn * 32 + nf * 8 + 2 * q;      // 0..127
                    const float2 bb = *reinterpret_cast<const float2*>(
                        b1 + jc * 128 + col);
                    const int blkc = col >> 3;
                    #pragma unroll
                    for (int mf = 0; mf < 2; mf++)
                        #pragma unroll
                        for (int hf = 0; hf < 2; hf++) {
                            const int row = wm * 32 + mf * 16 + r + 8 * hf;
                            const float v0 = fmaxf(c1[mf][nf][2 * hf]     + bb.x, 0.f);
                            const float v1 = fmaxf(c1[mf][nf][2 * hf + 1] + bb.y, 0.f);
                            const uint32_t ad = hb + row * 256 +
                                ((uint32_t)(blkc ^ (row & 7)) << 4) + ((col * 2) & 15);
                            asm volatile("st.shared.b32 [%0], %1;" ::
                                "r"(ad), "r"(packh(__float2half(v0), __float2half(v1)))
                                : "memory");
                            c1[mf][nf][2 * hf] = 0.f;
                            c1[mf][nf][2 * hf + 1] = 0.f;
                        }
                }
            }
        } else {
            chunk2h(buf, hb, s - 2, wm, wn, lane, c2);
        }
        __syncthreads();
    }

    // ---- final epilogue: transpose via smem, NCHW store + bias + residual ----
    float* sC = (float*)dsm;                  // 64 ch x 68 floats per half
    const int n  = m0 >> 12;
    const int sp0 = m0 & 4095;

    #pragma unroll 1
    for (int hh = 0; hh < 2; hh++) {
        if ((wn >> 1) == hh) {
            #pragma unroll
            for (int nf = 0; nf < 4; nf++) {
                const int cl = (wn & 1) * 32 + nf * 8 + 2 * q;
                #pragma unroll
                for (int mf = 0; mf < 2; mf++)
                    #pragma unroll
                    for (int hf = 0; hf < 2; hf++) {
                        const int ml = wm * 32 + mf * 16 + r + 8 * hf;
                        sC[cl * 68 + ml]       = c2[mf][nf][2 * hf];
                        sC[(cl + 1) * 68 + ml] = c2[mf][nf][2 * hf + 1];
                    }
            }
        }
        __syncthreads();
        #pragma unroll
        for (int qi = 0; qi < 4; qi++) {
            const int idx = qi * 256 + tid;
            const int j   = idx >> 4;          // 0..63
            const int m4  = (idx & 15) << 2;   // 0..60
            const int ch  = hh * 64 + j;
            const float bc = __ldg(&b2[ch]);
            const size_t g = ((size_t)(n * C_DIM + ch) << 12) + sp0 + m4;
            float4 v  = *reinterpret_cast<const float4*>(&sC[j * 68 + m4]);
            float4 xv = *reinterpret_cast<const float4*>(x + g);
            float4 o;
            o.x = v.x + xv.x + bc;
            o.y = v.y + xv.y + bc;
            o.z = v.z + xv.z + bc;
            o.w = v.w + xv.w + bc;
            *reinterpret_cast<float4*>(out + g) = o;
        }
        __syncthreads();
    }
}

// ---------------------------------------------------------------------------
extern "C" void kernel_launch(void* const* d_in, const int* in_sizes, int n_in,
                              void* d_out, int out_size)
{
    const float* x     = (const float*)d_in[0];
    const float* dw_w  = (const float*)d_in[1];
    const float* dw_b  = (const float*)d_in[2];
    const float* gamma = (const float*)d_in[3];
    const float* beta  = (const float*)d_in[4];
    const float* pw1_w = (const float*)d_in[5];
    const float* pw1_b = (const float*)d_in[6];
    const float* pw2_w = (const float*)d_in[7];
    const float* pw2_b = (const float*)d_in[8];
    float* out = (float*)d_out;

    static bool attr_done = false;
    if (!attr_done) {
        cudaFuncSetAttribute(dwln_kernel, cudaFuncAttributeMaxDynamicSharedMemorySize, DWLN_SMEM);
        cudaFuncSetAttribute(fused_mlp, cudaFuncAttributeMaxDynamicSharedMemorySize, SMEM_F);
        attr_done = true;
    }

    wconv_kernel<<<(D_BOT * C_DIM + 255) / 256, 256>>>(pw1_w, pw2_w);
    dwln_kernel<<<N_IMG * H_DIM / 2, 256, DWLN_SMEM>>>(x, dw_w, dw_b, gamma, beta);
    fused_mlp<<<M_TOT / 64, 256, SMEM_F>>>(x, pw1_b, pw2_b, out);
}

// round 14
// speedup vs baseline: 2.0502x; 1.0138x over previous
#include <cuda_runtime.h>
#include <cuda_fp16.h>
#include <cstdint>

// ConvNeXt block: dwconv7x7 -> LN -> fused 1x1 MLP (fp16 mma.sync) -> residual
#define N_IMG 32
#define C_DIM 128
#define H_DIM 64
#define W_DIM 64
#define D_BOT 512
#define EPS_LN 1e-5f
#define M_TOT (N_IMG * H_DIM * W_DIM)   // 131072

// ---------------- scratch (device globals; no allocs) ----------------------
__device__ __half g_y[(size_t)M_TOT * C_DIM];
__device__ __half g_w1h[D_BOT * C_DIM];
__device__ __half g_w2h[C_DIM * D_BOT];

// ---------------- helpers ---------------------------------------------------
__device__ __forceinline__ uint32_t s2u(const void* p) {
    uint32_t a;
    asm("{ .reg .u64 t; cvta.to.shared.u64 t, %1; cvt.u32.u64 %0, t; }"
        : "=r"(a) : "l"(p));
    return a;
}
__device__ __forceinline__ void cpasync16(uint32_t dst, const void* src) {
    asm volatile("cp.async.cg.shared.global [%0], [%1], 16;" :: "r"(dst), "l"(src));
}
__device__ __forceinline__ void ldsm4(uint32_t* r, uint32_t addr) {
    asm volatile("ldmatrix.sync.aligned.m8n8.x4.shared.b16 {%0,%1,%2,%3}, [%4];"
                 : "=r"(r[0]), "=r"(r[1]), "=r"(r[2]), "=r"(r[3]) : "r"(addr));
}
__device__ __forceinline__ void mma_f16(float* c, uint32_t a0, uint32_t a1,
                                        uint32_t a2, uint32_t a3,
                                        uint32_t b0, uint32_t b1) {
    asm volatile(
        "mma.sync.aligned.m16n8k16.row.col.f32.f16.f16.f32 "
        "{%0,%1,%2,%3}, {%4,%5,%6,%7}, {%8,%9}, {%0,%1,%2,%3};"
        : "+f"(c[0]), "+f"(c[1]), "+f"(c[2]), "+f"(c[3])
        : "r"(a0), "r"(a1), "r"(a2), "r"(a3), "r"(b0), "r"(b1));
}
__device__ __forceinline__ uint32_t packh(__half a, __half b) {
    return (uint32_t)__half_as_ushort(a) | ((uint32_t)__half_as_ushort(b) << 16);
}
// ---- f32x2 packed-FMA helpers ----
__device__ __forceinline__ unsigned long long splat2(float x) {
    unsigned long long r;
    unsigned int xi = __float_as_uint(x);
    asm("mov.b64 %0, {%1, %1};" : "=l"(r) : "r"(xi));
    return r;
}
__device__ __forceinline__ unsigned long long pack2(float a, float b) {
    unsigned long long r;
    asm("mov.b64 %0, {%1, %2};" : "=l"(r) : "f"(a), "f"(b));
    return r;
}
__device__ __forceinline__ void ffma2(unsigned long long& d,
                                      unsigned long long a,
                                      unsigned long long b) {
    asm("fma.rn.f32x2 %0, %1, %2, %0;" : "+l"(d) : "l"(a), "l"(b));
}
__device__ __forceinline__ float2 u2f(unsigned long long u) {
    float2 f;
    asm("mov.b64 {%0, %1}, %2;" : "=f"(f.x), "=f"(f.y) : "l"(u));
    return f;
}

// ---------------------------------------------------------------------------
// Kernel 0: weights -> fp16
// ---------------------------------------------------------------------------
__global__ __launch_bounds__(256) void wconv_kernel(const float* __restrict__ w1,
                                                    const float* __restrict__ w2) {
    int i = blockIdx.x * 256 + threadIdx.x;
    if (i < D_BOT * C_DIM) {
        g_w1h[i] = __float2half(w1[i]);
        g_w2h[i] = __float2half(w2[i]);
    }
}

// ---------------------------------------------------------------------------
// Kernel 1: dwconv 7x7 + bias + LN -> fp16 NHWC. (unchanged from R12)
// ---------------------------------------------------------------------------
#define DW_SY    (128 * 129)                 // floats
#define DWLN_SMEM (DW_SY * 4)                // 66048 B

__device__ __forceinline__ void dw_accum(
    const float4 v1, const float* wcur, const float* wprev,
    int l, int li, unsigned long long acc[4])
{
    float by = __shfl_sync(0xffffffffu, v1.y, (l - 1) & 31);
    float bz = __shfl_sync(0xffffffffu, v1.z, (l - 1) & 31);
    float bw = __shfl_sync(0xffffffffu, v1.w, (l - 1) & 31);
    float cx = __shfl_sync(0xffffffffu, v1.x, (l + 1) & 31);
    float cy = __shfl_sync(0xffffffffu, v1.y, (l + 1) & 31);
    float cz = __shfl_sync(0xffffffffu, v1.z, (l + 1) & 31);
    if (li == 0)  { by = 0.f; bz = 0.f; bw = 0.f; }
    if (li == 15) { cx = 0.f; cy = 0.f; cz = 0.f; }
    const float s[10] = {by, bz, bw, v1.x, v1.y, v1.z, v1.w, cx, cy, cz};
    unsigned long long sp[10];
    #pragma unroll
    for (int k = 0; k < 10; k++) sp[k] = splat2(s[k]);
    #pragma unroll
    for (int dx = 0; dx < 7; dx++) {
        const unsigned long long wp = pack2(wcur[dx], wprev[dx]);
        #pragma unroll
        for (int j = 0; j < 4; j++) ffma2(acc[j], sp[dx + j], wp);
    }
}

__global__ __launch_bounds__(256, 3) void dwln_kernel(
    const float* __restrict__ x, const float* __restrict__ dw_w,
    const float* __restrict__ dw_b, const float* __restrict__ gamma,
    const float* __restrict__ beta)
{
    extern __shared__ float s_y[];      // [128 pos][129]

    const int b = blockIdx.x;
    const int n  = b >> 5;
    const int h0 = (b & 31) << 1;
    const int tid = threadIdx.x;
    const int wg = tid >> 5;
    const int l  = tid & 31;
    const int half = l >> 4;
    const int li = l & 15;
    const int slot = wg * 2 + half;

    #pragma unroll 1
    for (int it = 0; it < 4; it++) {
        const int c0 = it * 32 + slot;
        const int c1 = c0 + 16;
        const float* xc0 = x + ((size_t)n * C_DIM + c0) * (H_DIM * W_DIM);
        const float* xc1 = x + ((size_t)n * C_DIM + c1) * (H_DIM * W_DIM);
        const float* wq0 = dw_w + c0 * 49;
        const float* wq1 = dw_w + c1 * 49;

        unsigned long long acc0[4], acc1[4];
        {
            const float bi0 = __ldg(&dw_b[c0]);
            const float bi1 = __ldg(&dw_b[c1]);
            #pragma unroll
            for (int j = 0; j < 4; j++) { acc0[j] = splat2(bi0); acc1[j] = splat2(bi1); }
        }
        float wprev0[7], wprev1[7];
        #pragma unroll
        for (int k = 0; k < 7; k++) { wprev0[k] = 0.f; wprev1[k] = 0.f; }

        #pragma unroll 1
        for (int dy = 0; dy < 8; dy++) {
            const int hh = h0 - 3 + dy;
            float4 v1a = make_float4(0.f, 0.f, 0.f, 0.f);
            float4 v1b = v1a;
            if (hh >= 0 && hh < H_DIM) {
                v1a = *reinterpret_cast<const float4*>(xc0 + hh * W_DIM + 4 * li);
                v1b = *reinterpret_cast<const float4*>(xc1 + hh * W_DIM + 4 * li);
            }
            float wcur0[7], wcur1[7];
            #pragma unroll
            for (int k = 0; k < 7; k++) {
                wcur0[k] = (dy < 7) ? __ldg(&wq0[dy * 7 + k]) : 0.f;
                wcur1[k] = (dy < 7) ? __ldg(&wq1[dy * 7 + k]) : 0.f;
            }
            dw_accum(v1a, wcur0, wprev0, l, li, acc0);
            dw_accum(v1b, wcur1, wprev1, l, li, acc1);
            #pragma unroll
            for (int k = 0; k < 7; k++) { wprev0[k] = wcur0[k]; wprev1[k] = wcur1[k]; }
        }
        #pragma unroll
        for (int j = 0; j < 4; j++) {
            const float2 f0 = u2f(acc0[j]);
            const float2 f1 = u2f(acc1[j]);
            s_y[(4 * li + j) * 129 + c0]      = f0.x;
            s_y[(64 + 4 * li + j) * 129 + c0] = f0.y;
            s_y[(4 * li + j) * 129 + c1]      = f1.x;
            s_y[(64 + 4 * li + j) * 129 + c1] = f1.y;
        }
    }
    __syncthreads();

    for (int wi = 0; wi < 16; wi++) {
        const int p = wg * 16 + wi;
        float v[4], s = 0.f, sq = 0.f;
        #pragma unroll
        for (int i = 0; i < 4; i++) {
            v[i] = s_y[p * 129 + l + 32 * i];
            s += v[i];
            sq += v[i] * v[i];
        }
        #pragma unroll
        for (int o = 16; o > 0; o >>= 1) {
            s  += __shfl_xor_sync(0xffffffffu, s, o);
            sq += __shfl_xor_sync(0xffffffffu, sq, o);
        }
        const float mu  = s * (1.f / 128.f);
        const float var = sq * (1.f / 128.f) - mu * mu;
        const float rs  = rsqrtf(var + EPS_LN);
        const size_t row =
            (((size_t)n * H_DIM + h0 + (p >> 6)) * W_DIM + (p & 63)) * C_DIM;
        #pragma unroll
        for (int i = 0; i < 4; i++) {
            const int cix = l + 32 * i;
            const float val = (v[i] - mu) * rs * __ldg(&gamma[cix]) + __ldg(&beta[cix]);
            g_y[row + cix] = __float2half(val);
        }
    }
}

// ---------------------------------------------------------------------------
// Fused MLP v2 (fixed): CTA = 64 m-rows.
//   - y tile (64 rows x 128 halves) persistent in smem, row stride 272B.
//   - 16 phases stage only the weight chunk (W1 or W2), 3-deep pipeline.
//   - h tile (64 x 128 fp16) XOR-swizzled, row stride 256B.
// smem: [0, 55296) 3 x B staging, [55296, 72704) y tile, [72704, 89088) h tile.
// ---------------------------------------------------------------------------
#define ROWB  144
#define ROWY  272
#define BMAT  (128 * ROWB)          // 18432 B
#define Y_OFF (3 * BMAT)            // 55296
#define H_OFF (Y_OFF + 64 * ROWY)   // 72704
#define SMEM_F (H_OFF + 64 * 256)   // 89088

__device__ __forceinline__ void stage_y(int m0, uint32_t yb) {
    const int tid = threadIdx.x;
    #pragma unroll
    for (int p = 0; p < 4; p++) {
        const int idx = p * 256 + tid;          // 0..1023
        const int row = idx >> 4, seg = idx & 15;
        cpasync16(yb + row * ROWY + seg * 16,
                  g_y + (size_t)(m0 + row) * C_DIM + seg * 8);
    }
}

// stage one 128-row x 64-k weight chunk (W1 for s<2, W2 for s>=2)
__device__ __forceinline__ void stage_B(int t, uint32_t buf) {
    const int tid = threadIdx.x;
    const int jc = t >> 2, s = t & 3;
    const __half* src;
    int k0;
    if (s < 2) { src = g_w1h + (size_t)(jc * 128) * C_DIM; k0 = s * 64; }
    else       { src = g_w2h;                              k0 = jc * 128 + (s - 2) * 64; }
    const int ld = (s < 2) ? C_DIM : D_BOT;
    #pragma unroll
    for (int p = 0; p < 4; p++) {
        const int idx = p * 256 + tid;
        const int row = idx >> 3, seg = idx & 7;
        cpasync16(buf + row * ROWB + seg * 16,
                  src + (size_t)row * ld + k0 + seg * 8);
    }
}

// gemm1 compute: A from persistent y smem (stride ROWY, col offset aCol), B staged
__device__ __forceinline__ void chunk1(uint32_t yb, int aCol, uint32_t bBase,
                                       int wm, int wn, int lane, float c[2][4][4])
{
    #pragma unroll
    for (int ks = 0; ks < 4; ks++) {
        const uint32_t aAddr = yb + (wm * 32 + (lane & 15)) * ROWY +
                               aCol + ks * 32 + (lane >> 4) * 16;
        const uint32_t bAddr = bBase +
                               (wn * 32 + (lane & 7) + (lane >> 4) * 8) * ROWB +
                               ks * 32 + ((lane >> 3) & 1) * 16;
        uint32_t Af[2][4], Bf[2][4];
        #pragma unroll
        for (int mf = 0; mf < 2; mf++) ldsm4(Af[mf], aAddr + mf * (16 * ROWY));
        #pragma unroll
        for (int n2 = 0; n2 < 2; n2++) ldsm4(Bf[n2], bAddr + n2 * (16 * ROWB));
        #pragma unroll
        for (int mf = 0; mf < 2; mf++)
            #pragma unroll
            for (int nf = 0; nf < 4; nf++)
                mma_f16(c[mf][nf], Af[mf][0], Af[mf][1], Af[mf][2], Af[mf][3],
                        Bf[nf >> 1][(nf & 1) * 2], Bf[nf >> 1][(nf & 1) * 2 + 1]);
    }
}

// gemm2 compute: A from swizzled h smem (row stride 256B), B staged
__device__ __forceinline__ void chunk2h(uint32_t bBase, uint32_t hb, int kc,
                                        int wm, int wn, int lane, float c[2][4][4])
{
    #pragma unroll
    for (int ks = 0; ks < 4; ks++) {
        const int blk = kc * 8 + ks * 2 + (lane >> 4);
        const uint32_t aAddr0 = hb + (wm * 32 + (lane & 15)) * 256 +
                                (uint32_t)((blk ^ (lane & 7)) << 4);
        const uint32_t bAddr = bBase +
                               (wn * 32 + (lane & 7) + (lane >> 4) * 8) * ROWB +
                               ks * 32 + ((lane >> 3) & 1) * 16;
        uint32_t Af[2][4], Bf[2][4];
        #pragma unroll
        for (int mf = 0; mf < 2; mf++) ldsm4(Af[mf], aAddr0 + mf * (16 * 256));
        #pragma unroll
        for (int n2 = 0; n2 < 2; n2++) ldsm4(Bf[n2], bAddr + n2 * (16 * ROWB));
        #pragma unroll
        for (int mf = 0; mf < 2; mf++)
            #pragma unroll
            for (int nf = 0; nf < 4; nf++)
                mma_f16(c[mf][nf], Af[mf][0], Af[mf][1], Af[mf][2], Af[mf][3],
                        Bf[nf >> 1][(nf & 1) * 2], Bf[nf >> 1][(nf & 1) * 2 + 1]);
    }
}

__global__ __launch_bounds__(256, 2) void fused_mlp(
    const float* __restrict__ x, const float* __restrict__ b1,
    const float* __restrict__ b2, float* __restrict__ out)
{
    extern __shared__ char dsm[];
    const uint32_t sb = s2u(dsm);
    const uint32_t yb = sb + Y_OFF;
    const uint32_t hb = sb + H_OFF;

    const int tid = threadIdx.x;
    const int wid = tid >> 5, lane = tid & 31;
    const int wm = wid >> 2, wn = wid & 3;
    const int r = lane >> 2, q = lane & 3;
    const int m0 = blockIdx.x << 6;

    float c1[2][4][4], c2[2][4][4];
    #pragma unroll
    for (int a = 0; a < 2; a++)
        #pragma unroll
        for (int b_ = 0; b_ < 4; b_++)
            #pragma unroll
            for (int d = 0; d < 4; d++) { c1[a][b_][d] = 0.f; c2[a][b_][d] = 0.f; }

    stage_y(m0, yb);
    asm volatile("cp.async.commit_group;");
    stage_B(0, sb);
    asm volatile("cp.async.commit_group;");
    stage_B(1, sb + BMAT);
    asm volatile("cp.async.commit_group;");

    #pragma unroll 1
    for (int t = 0; t < 16; t++) {
        if (t + 2 < 16) {
            stage_B(t + 2, sb + ((t + 2) % 3) * BMAT);
            asm volatile("cp.async.commit_group;");
            asm volatile("cp.async.wait_group 2;");
        } else if (t + 2 == 16) {
            asm volatile("cp.async.wait_group 1;");
        } else {
            asm volatile("cp.async.wait_group 0;");
        }
        __syncthreads();
        const uint32_t buf = sb + (t % 3) * BMAT;
        const int jc = t >> 2, s = t & 3;
        if (s < 2) {
            chunk1(yb, s * 128, buf, wm, wn, lane, c1);
            if (s == 1) {
                // h epilogue: bias + relu -> fp16 into swizzled h smem
                #pragma unroll
                for (int nf = 0; nf < 4; nf++) {
                    const int col = wn * 32 + nf * 8 + 2 * q;      // 0..127
                    const float2 bb = *reinterpret_cast<const float2*>(
                        b1 + jc * 128 + col);
                    const int blkc = col >> 3;
                    #pragma unroll
                    for (int mf = 0; mf < 2; mf++)
                        #pragma unroll
                        for (int hf = 0; hf < 2; hf++) {
                            const int row = wm * 32 + mf * 16 + r + 8 * hf;
                            const float v0 = fmaxf(c1[mf][nf][2 * hf]     + bb.x, 0.f);
                            const float v1 = fmaxf(c1[mf][nf][2 * hf + 1] + bb.y, 0.f);
                            const uint32_t ad = hb + row * 256 +
                                ((uint32_t)(blkc ^ (row & 7)) << 4) + ((col * 2) & 15);
                            asm volatile("st.shared.b32 [%0], %1;" ::
                                "r"(ad), "r"(packh(__float2half(v0), __float2half(v1)))
                                : "memory");
                            c1[mf][nf][2 * hf] = 0.f;
                            c1[mf][nf][2 * hf + 1] = 0.f;
                        }
                }
            }
        } else {
            chunk2h(buf, hb, s - 2, wm, wn, lane, c2);
        }
        __syncthreads();
    }

    // ---- final epilogue: transpose via smem, NCHW store + bias + residual ----
    float* sC = (float*)dsm;                  // 64 ch x 68 floats per half
    const int n  = m0 >> 12;
    const int sp0 = m0 & 4095;

    #pragma unroll 1
    for (int hh = 0; hh < 2; hh++) {
        if ((wn >> 1) == hh) {
            #pragma unroll
            for (int nf = 0; nf < 4; nf++) {
                const int cl = (wn & 1) * 32 + nf * 8 + 2 * q;
                #pragma unroll
                for (int mf = 0; mf < 2; mf++)
                    #pragma unroll
                    for (int hf = 0; hf < 2; hf++) {
                        const int ml = wm * 32 + mf * 16 + r + 8 * hf;
                        sC[cl * 68 + ml]       = c2[mf][nf][2 * hf];
                        sC[(cl + 1) * 68 + ml] = c2[mf][nf][2 * hf + 1];
                    }
            }
        }
        __syncthreads();
        #pragma unroll
        for (int qi = 0; qi < 4; qi++) {
            const int idx = qi * 256 + tid;
            const int j   = idx >> 4;          // 0..63
            const int m4  = (idx & 15) << 2;   // 0..60
            const int ch  = hh * 64 + j;
            const float bc = __ldg(&b2[ch]);
            const size_t g = ((size_t)(n * C_DIM + ch) << 12) + sp0 + m4;
            float4 v  = *reinterpret_cast<const float4*>(&sC[j * 68 + m4]);
            float4 xv = *reinterpret_cast<const float4*>(x + g);
            float4 o;
            o.x = v.x + xv.x + bc;
            o.y = v.y + xv.y + bc;
            o.z = v.z + xv.z + bc;
            o.w = v.w + xv.w + bc;
            *reinterpret_cast<float4*>(out + g) = o;
        }
        __syncthreads();
    }
}

// ---------------------------------------------------------------------------
extern "C" void kernel_launch(void* const* d_in, const int* in_sizes, int n_in,
                              void* d_out, int out_size)
{
    const float* x     = (const float*)d_in[0];
    const float* dw_w  = (const float*)d_in[1];
    const float* dw_b  = (const float*)d_in[2];
    const float* gamma = (const float*)d_in[3];
    const float* beta  = (const float*)d_in[4];
    const float* pw1_w = (const float*)d_in[5];
    const float* pw1_b = (const float*)d_in[6];
    const float* pw2_w = (const float*)d_in[7];
    const float* pw2_b = (const float*)d_in[8];
    float* out = (float*)d_out;

    static bool attr_done = false;
    if (!attr_done) {
        cudaFuncSetAttribute(dwln_kernel, cudaFuncAttributeMaxDynamicSharedMemorySize, DWLN_SMEM);
        cudaFuncSetAttribute(fused_mlp, cudaFuncAttributeMaxDynamicSharedMemorySize, SMEM_F);
        attr_done = true;
    }

    wconv_kernel<<<(D_BOT * C_DIM + 255) / 256, 256>>>(pw1_w, pw2_w);
    dwln_kernel<<<N_IMG * H_DIM / 2, 256, DWLN_SMEM>>>(x, dw_w, dw_b, gamma, beta);
    fused_mlp<<<M_TOT / 64, 256, SMEM_F>>>(x, pw1_b, pw2_b, out);
}

// round 15
// speedup vs baseline: 2.1435x; 1.0455x over previous
#include <cuda_runtime.h>
#include <cuda_fp16.h>
#include <cstdint>

// ConvNeXt block: dwconv7x7 -> LN -> fused 1x1 MLP (fp16 mma.sync) -> residual
#define N_IMG 32
#define C_DIM 128
#define H_DIM 64
#define W_DIM 64
#define D_BOT 512
#define EPS_LN 1e-5f
#define M_TOT (N_IMG * H_DIM * W_DIM)   // 131072

// ---------------- scratch (device globals; no allocs) ----------------------
__device__ __half g_y[(size_t)M_TOT * C_DIM];
__device__ __half g_w1h[D_BOT * C_DIM];
__device__ __half g_w2h[C_DIM * D_BOT];

// ---------------- helpers ---------------------------------------------------
__device__ __forceinline__ uint32_t s2u(const void* p) {
    uint32_t a;
    asm("{ .reg .u64 t; cvta.to.shared.u64 t, %1; cvt.u32.u64 %0, t; }"
        : "=r"(a) : "l"(p));
    return a;
}
__device__ __forceinline__ void cpasync16(uint32_t dst, const void* src) {
    asm volatile("cp.async.cg.shared.global [%0], [%1], 16;" :: "r"(dst), "l"(src));
}
__device__ __forceinline__ void ldsm4(uint32_t* r, uint32_t addr) {
    asm volatile("ldmatrix.sync.aligned.m8n8.x4.shared.b16 {%0,%1,%2,%3}, [%4];"
                 : "=r"(r[0]), "=r"(r[1]), "=r"(r[2]), "=r"(r[3]) : "r"(addr));
}
__device__ __forceinline__ void mma_f16(float* c, uint32_t a0, uint32_t a1,
                                        uint32_t a2, uint32_t a3,
                                        uint32_t b0, uint32_t b1) {
    asm volatile(
        "mma.sync.aligned.m16n8k16.row.col.f32.f16.f16.f32 "
        "{%0,%1,%2,%3}, {%4,%5,%6,%7}, {%8,%9}, {%0,%1,%2,%3};"
        : "+f"(c[0]), "+f"(c[1]), "+f"(c[2]), "+f"(c[3])
        : "r"(a0), "r"(a1), "r"(a2), "r"(a3), "r"(b0), "r"(b1));
}
__device__ __forceinline__ uint32_t packh(__half a, __half b) {
    return (uint32_t)__half_as_ushort(a) | ((uint32_t)__half_as_ushort(b) << 16);
}
// ---- f32x2 packed-FMA helpers ----
__device__ __forceinline__ unsigned long long splat2(float x) {
    unsigned long long r;
    unsigned int xi = __float_as_uint(x);
    asm("mov.b64 %0, {%1, %1};" : "=l"(r) : "r"(xi));
    return r;
}
__device__ __forceinline__ unsigned long long pack2(float a, float b) {
    unsigned long long r;
    asm("mov.b64 %0, {%1, %2};" : "=l"(r) : "f"(a), "f"(b));
    return r;
}
__device__ __forceinline__ void ffma2(unsigned long long& d,
                                      unsigned long long a,
                                      unsigned long long b) {
    asm("fma.rn.f32x2 %0, %1, %2, %0;" : "+l"(d) : "l"(a), "l"(b));
}
__device__ __forceinline__ float2 u2f(unsigned long long u) {
    float2 f;
    asm("mov.b64 {%0, %1}, %2;" : "=f"(f.x), "=f"(f.y) : "l"(u));
    return f;
}

// ---------------------------------------------------------------------------
// Kernel 0: weights -> fp16
// ---------------------------------------------------------------------------
__global__ __launch_bounds__(256) void wconv_kernel(const float* __restrict__ w1,
                                                    const float* __restrict__ w2) {
    int i = blockIdx.x * 256 + threadIdx.x;
    if (i < D_BOT * C_DIM) {
        g_w1h[i] = __float2half(w1[i]);
        g_w2h[i] = __float2half(w2[i]);
    }
}

// ---------------------------------------------------------------------------
// Kernel 1: dwconv 7x7 + bias + LN -> fp16 NHWC. (unchanged from R14)
// ---------------------------------------------------------------------------
#define DW_SY    (128 * 129)                 // floats
#define DWLN_SMEM (DW_SY * 4)                // 66048 B

__device__ __forceinline__ void dw_accum(
    const float4 v1, const float* wcur, const float* wprev,
    int l, int li, unsigned long long acc[4])
{
    float by = __shfl_sync(0xffffffffu, v1.y, (l - 1) & 31);
    float bz = __shfl_sync(0xffffffffu, v1.z, (l - 1) & 31);
    float bw = __shfl_sync(0xffffffffu, v1.w, (l - 1) & 31);
    float cx = __shfl_sync(0xffffffffu, v1.x, (l + 1) & 31);
    float cy = __shfl_sync(0xffffffffu, v1.y, (l + 1) & 31);
    float cz = __shfl_sync(0xffffffffu, v1.z, (l + 1) & 31);
    if (li == 0)  { by = 0.f; bz = 0.f; bw = 0.f; }
    if (li == 15) { cx = 0.f; cy = 0.f; cz = 0.f; }
    const float s[10] = {by, bz, bw, v1.x, v1.y, v1.z, v1.w, cx, cy, cz};
    unsigned long long sp[10];
    #pragma unroll
    for (int k = 0; k < 10; k++) sp[k] = splat2(s[k]);
    #pragma unroll
    for (int dx = 0; dx < 7; dx++) {
        const unsigned long long wp = pack2(wcur[dx], wprev[dx]);
        #pragma unroll
        for (int j = 0; j < 4; j++) ffma2(acc[j], sp[dx + j], wp);
    }
}

__global__ __launch_bounds__(256, 3) void dwln_kernel(
    const float* __restrict__ x, const float* __restrict__ dw_w,
    const float* __restrict__ dw_b, const float* __restrict__ gamma,
    const float* __restrict__ beta)
{
    extern __shared__ float s_y[];      // [128 pos][129]

    const int b = blockIdx.x;
    const int n  = b >> 5;
    const int h0 = (b & 31) << 1;
    const int tid = threadIdx.x;
    const int wg = tid >> 5;
    const int l  = tid & 31;
    const int half = l >> 4;
    const int li = l & 15;
    const int slot = wg * 2 + half;

    #pragma unroll 1
    for (int it = 0; it < 4; it++) {
        const int c0 = it * 32 + slot;
        const int c1 = c0 + 16;
        const float* xc0 = x + ((size_t)n * C_DIM + c0) * (H_DIM * W_DIM);
        const float* xc1 = x + ((size_t)n * C_DIM + c1) * (H_DIM * W_DIM);
        const float* wq0 = dw_w + c0 * 49;
        const float* wq1 = dw_w + c1 * 49;

        unsigned long long acc0[4], acc1[4];
        {
            const float bi0 = __ldg(&dw_b[c0]);
            const float bi1 = __ldg(&dw_b[c1]);
            #pragma unroll
            for (int j = 0; j < 4; j++) { acc0[j] = splat2(bi0); acc1[j] = splat2(bi1); }
        }
        float wprev0[7], wprev1[7];
        #pragma unroll
        for (int k = 0; k < 7; k++) { wprev0[k] = 0.f; wprev1[k] = 0.f; }

        #pragma unroll 1
        for (int dy = 0; dy < 8; dy++) {
            const int hh = h0 - 3 + dy;
            float4 v1a = make_float4(0.f, 0.f, 0.f, 0.f);
            float4 v1b = v1a;
            if (hh >= 0 && hh < H_DIM) {
                v1a = *reinterpret_cast<const float4*>(xc0 + hh * W_DIM + 4 * li);
                v1b = *reinterpret_cast<const float4*>(xc1 + hh * W_DIM + 4 * li);
            }
            float wcur0[7], wcur1[7];
            #pragma unroll
            for (int k = 0; k < 7; k++) {
                wcur0[k] = (dy < 7) ? __ldg(&wq0[dy * 7 + k]) : 0.f;
                wcur1[k] = (dy < 7) ? __ldg(&wq1[dy * 7 + k]) : 0.f;
            }
            dw_accum(v1a, wcur0, wprev0, l, li, acc0);
            dw_accum(v1b, wcur1, wprev1, l, li, acc1);
            #pragma unroll
            for (int k = 0; k < 7; k++) { wprev0[k] = wcur0[k]; wprev1[k] = wcur1[k]; }
        }
        #pragma unroll
        for (int j = 0; j < 4; j++) {
            const float2 f0 = u2f(acc0[j]);
            const float2 f1 = u2f(acc1[j]);
            s_y[(4 * li + j) * 129 + c0]      = f0.x;
            s_y[(64 + 4 * li + j) * 129 + c0] = f0.y;
            s_y[(4 * li + j) * 129 + c1]      = f1.x;
            s_y[(64 + 4 * li + j) * 129 + c1] = f1.y;
        }
    }
    __syncthreads();

    for (int wi = 0; wi < 16; wi++) {
        const int p = wg * 16 + wi;
        float v[4], s = 0.f, sq = 0.f;
        #pragma unroll
        for (int i = 0; i < 4; i++) {
            v[i] = s_y[p * 129 + l + 32 * i];
            s += v[i];
            sq += v[i] * v[i];
        }
        #pragma unroll
        for (int o = 16; o > 0; o >>= 1) {
            s  += __shfl_xor_sync(0xffffffffu, s, o);
            sq += __shfl_xor_sync(0xffffffffu, sq, o);
        }
        const float mu  = s * (1.f / 128.f);
        const float var = sq * (1.f / 128.f) - mu * mu;
        const float rs  = rsqrtf(var + EPS_LN);
        const size_t row =
            (((size_t)n * H_DIM + h0 + (p >> 6)) * W_DIM + (p & 63)) * C_DIM;
        #pragma unroll
        for (int i = 0; i < 4; i++) {
            const int cix = l + 32 * i;
            const float val = (v[i] - mu) * rs * __ldg(&gamma[cix]) + __ldg(&beta[cix]);
            g_y[row + cix] = __float2half(val);
        }
    }
}

// ---------------------------------------------------------------------------
// Fused MLP v3: CTA = 64 m-rows. 4-deep B ring + ONE __syncthreads per phase.
//   - y tile persistent (stride 272B), h tile XOR-swizzled (stride 256B).
// smem: [0, 73728) 4 x B staging, [73728, 91136) y tile, [91136, 107520) h.
// ---------------------------------------------------------------------------
#define ROWB  144
#define ROWY  272
#define BMAT  (128 * ROWB)          // 18432 B
#define Y_OFF (4 * BMAT)            // 73728
#define H_OFF (Y_OFF + 64 * ROWY)   // 91136
#define SMEM_F (H_OFF + 64 * 256)   // 107520

__device__ __forceinline__ void stage_y(int m0, uint32_t yb) {
    const int tid = threadIdx.x;
    #pragma unroll
    for (int p = 0; p < 4; p++) {
        const int idx = p * 256 + tid;          // 0..1023
        const int row = idx >> 4, seg = idx & 15;
        cpasync16(yb + row * ROWY + seg * 16,
                  g_y + (size_t)(m0 + row) * C_DIM + seg * 8);
    }
}

// stage one 128-row x 64-k weight chunk (W1 for s<2, W2 for s>=2)
__device__ __forceinline__ void stage_B(int t, uint32_t buf) {
    const int tid = threadIdx.x;
    const int jc = t >> 2, s = t & 3;
    const __half* src;
    int k0;
    if (s < 2) { src = g_w1h + (size_t)(jc * 128) * C_DIM; k0 = s * 64; }
    else       { src = g_w2h;                              k0 = jc * 128 + (s - 2) * 64; }
    const int ld = (s < 2) ? C_DIM : D_BOT;
    #pragma unroll
    for (int p = 0; p < 4; p++) {
        const int idx = p * 256 + tid;
        const int row = idx >> 3, seg = idx & 7;
        cpasync16(buf + row * ROWB + seg * 16,
                  src + (size_t)row * ld + k0 + seg * 8);
    }
}

// gemm1 compute: A from persistent y smem (stride ROWY, col offset aCol), B staged
__device__ __forceinline__ void chunk1(uint32_t yb, int aCol, uint32_t bBase,
                                       int wm, int wn, int lane, float c[2][4][4])
{
    #pragma unroll
    for (int ks = 0; ks < 4; ks++) {
        const uint32_t aAddr = yb + (wm * 32 + (lane & 15)) * ROWY +
                               aCol + ks * 32 + (lane >> 4) * 16;
        const uint32_t bAddr = bBase +
                               (wn * 32 + (lane & 7) + (lane >> 4) * 8) * ROWB +
                               ks * 32 + ((lane >> 3) & 1) * 16;
        uint32_t Af[2][4], Bf[2][4];
        #pragma unroll
        for (int mf = 0; mf < 2; mf++) ldsm4(Af[mf], aAddr + mf * (16 * ROWY));
        #pragma unroll
        for (int n2 = 0; n2 < 2; n2++) ldsm4(Bf[n2], bAddr + n2 * (16 * ROWB));
        #pragma unroll
        for (int mf = 0; mf < 2; mf++)
            #pragma unroll
            for (int nf = 0; nf < 4; nf++)
                mma_f16(c[mf][nf], Af[mf][0], Af[mf][1], Af[mf][2], Af[mf][3],
                        Bf[nf >> 1][(nf & 1) * 2], Bf[nf >> 1][(nf & 1) * 2 + 1]);
    }
}

// gemm2 compute: A from swizzled h smem (row stride 256B), B staged
__device__ __forceinline__ void chunk2h(uint32_t bBase, uint32_t hb, int kc,
                                        int wm, int wn, int lane, float c[2][4][4])
{
    #pragma unroll
    for (int ks = 0; ks < 4; ks++) {
        const int blk = kc * 8 + ks * 2 + (lane >> 4);
        const uint32_t aAddr0 = hb + (wm * 32 + (lane & 15)) * 256 +
                                (uint32_t)((blk ^ (lane & 7)) << 4);
        const uint32_t bAddr = bBase +
                               (wn * 32 + (lane & 7) + (lane >> 4) * 8) * ROWB +
                               ks * 32 + ((lane >> 3) & 1) * 16;
        uint32_t Af[2][4], Bf[2][4];
        #pragma unroll
        for (int mf = 0; mf < 2; mf++) ldsm4(Af[mf], aAddr0 + mf * (16 * 256));
        #pragma unroll
        for (int n2 = 0; n2 < 2; n2++) ldsm4(Bf[n2], bAddr + n2 * (16 * ROWB));
        #pragma unroll
        for (int mf = 0; mf < 2; mf++)
            #pragma unroll
            for (int nf = 0; nf < 4; nf++)
                mma_f16(c[mf][nf], Af[mf][0], Af[mf][1], Af[mf][2], Af[mf][3],
                        Bf[nf >> 1][(nf & 1) * 2], Bf[nf >> 1][(nf & 1) * 2 + 1]);
    }
}

__global__ __launch_bounds__(256, 2) void fused_mlp(
    const float* __restrict__ x, const float* __restrict__ b1,
    const float* __restrict__ b2, float* __restrict__ out)
{
    extern __shared__ char dsm[];
    const uint32_t sb = s2u(dsm);
    const uint32_t yb = sb + Y_OFF;
    const uint32_t hb = sb + H_OFF;

    const int tid = threadIdx.x;
    const int wid = tid >> 5, lane = tid & 31;
    const int wm = wid >> 2, wn = wid & 3;
    const int r = lane >> 2, q = lane & 3;
    const int m0 = blockIdx.x << 6;

    float c1[2][4][4], c2[2][4][4];
    #pragma unroll
    for (int a = 0; a < 2; a++)
        #pragma unroll
        for (int b_ = 0; b_ < 4; b_++)
            #pragma unroll
            for (int d = 0; d < 4; d++) { c1[a][b_][d] = 0.f; c2[a][b_][d] = 0.f; }

    stage_y(m0, yb);
    asm volatile("cp.async.commit_group;");
    stage_B(0, sb);
    asm volatile("cp.async.commit_group;");
    stage_B(1, sb + BMAT);
    asm volatile("cp.async.commit_group;");

    #pragma unroll 1
    for (int t = 0; t < 16; t++) {
        if (t + 2 < 16) {
            stage_B(t + 2, sb + ((t + 2) & 3) * BMAT);
            asm volatile("cp.async.commit_group;");
            asm volatile("cp.async.wait_group 2;");
        } else if (t + 2 == 16) {
            asm volatile("cp.async.wait_group 1;");
        } else {
            asm volatile("cp.async.wait_group 0;");
        }
        __syncthreads();                       // single barrier per phase
        const uint32_t buf = sb + (t & 3) * BMAT;
        const int jc = t >> 2, s = t & 3;
        if (s < 2) {
            chunk1(yb, s * 128, buf, wm, wn, lane, c1);
            if (s == 1) {
                // h epilogue: bias + relu -> fp16 into swizzled h smem
                #pragma unroll
                for (int nf = 0; nf < 4; nf++) {
                    const int col = wn * 32 + nf * 8 + 2 * q;      // 0..127
                    const float2 bb = *reinterpret_cast<const float2*>(
                        b1 + jc * 128 + col);
                    const int blkc = col >> 3;
                    #pragma unroll
                    for (int mf = 0; mf < 2; mf++)
                        #pragma unroll
                        for (int hf = 0; hf < 2; hf++) {
                            const int row = wm * 32 + mf * 16 + r + 8 * hf;
                            const float v0 = fmaxf(c1[mf][nf][2 * hf]     + bb.x, 0.f);
                            const float v1 = fmaxf(c1[mf][nf][2 * hf + 1] + bb.y, 0.f);
                            const uint32_t ad = hb + row * 256 +
                                ((uint32_t)(blkc ^ (row & 7)) << 4) + ((col * 2) & 15);
                            asm volatile("st.shared.b32 [%0], %1;" ::
                                "r"(ad), "r"(packh(__float2half(v0), __float2half(v1)))
                                : "memory");
                            c1[mf][nf][2 * hf] = 0.f;
                            c1[mf][nf][2 * hf + 1] = 0.f;
                        }
                }
            }
        } else {
            chunk2h(buf, hb, s - 2, wm, wn, lane, c2);
        }
    }
    __syncthreads();

    // ---- final epilogue: transpose via smem, NCHW store + bias + residual ----
    float* sC = (float*)dsm;                  // 64 ch x 68 floats per half
    const int n  = m0 >> 12;
    const int sp0 = m0 & 4095;

    #pragma unroll 1
    for (int hh = 0; hh < 2; hh++) {
        if ((wn >> 1) == hh) {
            #pragma unroll
            for (int nf = 0; nf < 4; nf++) {
                const int cl = (wn & 1) * 32 + nf * 8 + 2 * q;
                #pragma unroll
                for (int mf = 0; mf < 2; mf++)
                    #pragma unroll
                    for (int hf = 0; hf < 2; hf++) {
                        const int ml = wm * 32 + mf * 16 + r + 8 * hf;
                        sC[cl * 68 + ml]       = c2[mf][nf][2 * hf];
                        sC[(cl + 1) * 68 + ml] = c2[mf][nf][2 * hf + 1];
                    }
            }
        }
        __syncthreads();
        #pragma unroll
        for (int qi = 0; qi < 4; qi++) {
            const int idx = qi * 256 + tid;
            const int j   = idx >> 4;          // 0..63
            const int m4  = (idx & 15) << 2;   // 0..60
            const int ch  = hh * 64 + j;
            const float bc = __ldg(&b2[ch]);
            const size_t g = ((size_t)(n * C_DIM + ch) << 12) + sp0 + m4;
            float4 v  = *reinterpret_cast<const float4*>(&sC[j * 68 + m4]);
            float4 xv = *reinterpret_cast<const float4*>(x + g);
            float4 o;
            o.x = v.x + xv.x + bc;
            o.y = v.y + xv.y + bc;
            o.z = v.z + xv.z + bc;
            o.w = v.w + xv.w + bc;
            *reinterpret_cast<float4*>(out + g) = o;
        }
        __syncthreads();
    }
}

// ---------------------------------------------------------------------------
extern "C" void kernel_launch(void* const* d_in, const int* in_sizes, int n_in,
                              void* d_out, int out_size)
{
    const float* x     = (const float*)d_in[0];
    const float* dw_w  = (const float*)d_in[1];
    const float* dw_b  = (const float*)d_in[2];
    const float* gamma = (const float*)d_in[3];
    const float* beta  = (const float*)d_in[4];
    const float* pw1_w = (const float*)d_in[5];
    const float* pw1_b = (const float*)d_in[6];
    const float* pw2_w = (const float*)d_in[7];
    const float* pw2_b = (const float*)d_in[8];
    float* out = (float*)d_out;

    static bool attr_done = false;
    if (!attr_done) {
        cudaFuncSetAttribute(dwln_kernel, cudaFuncAttributeMaxDynamicSharedMemorySize, DWLN_SMEM);
        cudaFuncSetAttribute(fused_mlp, cudaFuncAttributeMaxDynamicSharedMemorySize, SMEM_F);
        attr_done = true;
    }

    wconv_kernel<<<(D_BOT * C_DIM + 255) / 256, 256>>>(pw1_w, pw2_w);
    dwln_kernel<<<N_IMG * H_DIM / 2, 256, DWLN_SMEM>>>(x, dw_w, dw_b, gamma, beta);
    fused_mlp<<<M_TOT / 64, 256, SMEM_F>>>(x, pw1_b, pw2_b, out);
}